// round 13
// baseline (speedup 1.0000x reference)
#include <cuda_runtime.h>
#include <cstdint>
#include <math.h>

#define NTOK 6144
#define DV   1024
#define DA   128
#define DC   (DV + DA)   // 1152
#define DH   1024
#define APP  20
#define BANDW 39
#define BANDP 40

// ---------------- scratch (static device globals; no allocation) -------------
__device__ float g_Kv [NTOK * DV];
__device__ float g_Qv [NTOK * DV];
__device__ float g_Vv [NTOK * DV];
__device__ float g_Yv [NTOK * DV];
__device__ float g_Yov[NTOK * DV];
__device__ float g_Ka [NTOK * DA];
__device__ float g_Qa [NTOK * DA];
__device__ float g_Va [NTOK * DA];
__device__ float g_Ya [NTOK * DA];
__device__ float g_Yoa[NTOK * DA];
__device__ float g_attv[NTOK * BANDP];
__device__ float g_atta[NTOK * BANDP];
__device__ float g_ycomb[NTOK * DC];
__device__ float g_h  [NTOK * DH];

// ======================= helpers =============================================
__device__ __forceinline__ uint32_t smem_u32(const void* p) {
    uint32_t r;
    asm("{ .reg .u64 t; cvta.to.shared.u64 t, %1; cvt.u32.u64 %0, t; }"
        : "=r"(r) : "l"(p));
    return r;
}

__device__ __forceinline__ uint32_t f2tf32(float x) {
    uint32_t r;
    asm("cvt.rna.tf32.f32 %0, %1;" : "=r"(r) : "f"(x));
    return r;
}

__device__ __forceinline__ void cp16(uint32_t dst, const void* src) {
    asm volatile("cp.async.ca.shared.global [%0], [%1], 16;" :: "r"(dst), "l"(src));
}
#define CP_COMMIT() asm volatile("cp.async.commit_group;" ::: "memory")
#define CP_WAIT(n)  asm volatile("cp.async.wait_group %0;" :: "n"(n) : "memory")

#define LDMX4(r0, r1, r2, r3, addr) \
    asm volatile("ldmatrix.sync.aligned.m8n8.x4.shared.b16 {%0,%1,%2,%3}, [%4];" \
                 : "=r"(r0), "=r"(r1), "=r"(r2), "=r"(r3) : "r"(addr))

#define MMA_TF32(c, a0, a1, a2, a3, b0, b1) \
    asm volatile("mma.sync.aligned.m16n8k8.row.col.f32.tf32.tf32.f32 " \
                 "{%0,%1,%2,%3}, {%4,%5,%6,%7}, {%8,%9}, {%0,%1,%2,%3};" \
                 : "+f"((c)[0]), "+f"((c)[1]), "+f"((c)[2]), "+f"((c)[3]) \
                 : "r"(a0), "r"(a1), "r"(a2), "r"(a3), "r"(b0), "r"(b1))

#define CVT_INPLACE(r) (r) = f2tf32(__uint_as_float(r))

// =============================================================================
// tgemm: C[z] = alpha[z] * A * B[z]^T (+bias)(relu), tf32 mma.
// 3-stage cp.async pipeline, compile-time stage offsets, ONE sync per chunk.
// CTA tile 128x128, BK=32, 8 warps (4M x 2N). smem: A0 A1 A2 B0 B1 B2, 128x36.
// =============================================================================
struct TG {
    const float* A;
    const float *B0, *B1, *B2;
    float *C0, *C1, *C2;
    float a0, a1, a2;
    const float* bias;
    int relu;
    int K, lda, ldb, ldc;
};

#define TILE_BYTES (128 * 36 * 4)           // 18432
#define TG_SMEM    (6 * TILE_BYTES)         // 110592

__global__ void __launch_bounds__(256)
tgemm(TG p)
{
    extern __shared__ char dsm[];
    const int tid  = threadIdx.x;
    const int lane = tid & 31;
    const int wid  = tid >> 5;
    const int wm   = wid & 3;
    const int wn   = wid >> 2;

    const int row0 = blockIdx.y * 128;
    const int col0 = blockIdx.x * 128;
    const int z = blockIdx.z;
    const float* B = (z == 0) ? p.B0 : (z == 1) ? p.B1 : p.B2;
    float*       C = (z == 0) ? p.C0 : (z == 1) ? p.C1 : p.C2;
    const float alpha = (z == 0) ? p.a0 : (z == 1) ? p.a1 : p.a2;

    const uint32_t sbase = smem_u32(dsm);

    const int lrow = tid >> 1;
    const int lcol = (tid & 1) * 16;
    const float* Ag = p.A + (size_t)(row0 + lrow) * p.lda + lcol;
    const float* Bg = B   + (size_t)(col0 + lrow) * p.ldb + lcol;
    const uint32_t a_stw = sbase + ((uint32_t)lrow * 36u + (uint32_t)lcol) * 4u;
    const uint32_t b_stw = a_stw + 3u * TILE_BYTES;

    const uint32_t a_ld0 = sbase +
        (((uint32_t)(wm * 32 + (lane & 15))) * 36u + ((uint32_t)(lane >> 4)) * 4u) * 4u;
    const uint32_t b_row = (uint32_t)(wn * 64 + (lane & 7) + ((lane & 16) >> 1));
    const uint32_t b_ld0 = sbase + 3u * TILE_BYTES +
        (b_row * 36u + (((uint32_t)lane >> 3) & 1u) * 4u) * 4u;

    float c[2][8][4];
#pragma unroll
    for (int mt = 0; mt < 2; mt++)
#pragma unroll
        for (int nt = 0; nt < 8; nt++)
#pragma unroll
            for (int q = 0; q < 4; q++) c[mt][nt][q] = 0.f;

    const int nch = p.K / 32;

    auto prefetch = [&](int ck, uint32_t off) {
        const float* ag = Ag + ck * 32;
        const float* bg = Bg + ck * 32;
#pragma unroll
        for (int i = 0; i < 4; i++) {
            cp16(a_stw + off + 16u * i, ag + 4 * i);
            cp16(b_stw + off + 16u * i, bg + 4 * i);
        }
        CP_COMMIT();
    };

    auto compute = [&](uint32_t off) {
        const uint32_t a_base = a_ld0 + off;
        const uint32_t b_base = b_ld0 + off;
#pragma unroll
        for (int k8 = 0; k8 < 4; k8++) {
            uint32_t a[2][4], b[4][4];
#pragma unroll
            for (int mt = 0; mt < 2; mt++) {
                LDMX4(a[mt][0], a[mt][1], a[mt][2], a[mt][3],
                      a_base + (uint32_t)mt * (16u * 36u * 4u) + (uint32_t)k8 * 32u);
#pragma unroll
                for (int q = 0; q < 4; q++) CVT_INPLACE(a[mt][q]);
            }
#pragma unroll
            for (int pr = 0; pr < 4; pr++) {
                LDMX4(b[pr][0], b[pr][1], b[pr][2], b[pr][3],
                      b_base + (uint32_t)pr * (16u * 36u * 4u) + (uint32_t)k8 * 32u);
#pragma unroll
                for (int q = 0; q < 4; q++) CVT_INPLACE(b[pr][q]);
            }
#pragma unroll
            for (int mt = 0; mt < 2; mt++)
#pragma unroll
                for (int nt = 0; nt < 8; nt++) {
                    const int pr = nt >> 1;
                    if (nt & 1) MMA_TF32(c[mt][nt], a[mt][0], a[mt][1], a[mt][2], a[mt][3],
                                         b[pr][2], b[pr][3]);
                    else        MMA_TF32(c[mt][nt], a[mt][0], a[mt][1], a[mt][2], a[mt][3],
                                         b[pr][0], b[pr][1]);
                }
        }
    };

    // prologue: chunks 0,1 -> stages 0,1
    prefetch(0, 0u);
    if (nch > 1) prefetch(1, TILE_BYTES);

#define TG_ITER(ck, BUF) do { \
        if ((ck) + 1 < nch) CP_WAIT(1); else CP_WAIT(0); \
        __syncthreads(); \
        if ((ck) + 2 < nch) prefetch((ck) + 2, (uint32_t)((((BUF) + 2) % 3) * TILE_BYTES)); \
        compute((uint32_t)((BUF) * TILE_BYTES)); \
    } while (0)

    for (int c0 = 0; c0 < nch; c0 += 3) {
        TG_ITER(c0, 0);
        if (c0 + 1 < nch) TG_ITER(c0 + 1, 1);
        if (c0 + 2 < nch) TG_ITER(c0 + 2, 2);
    }
#undef TG_ITER

    const int rbase = row0 + wm * 32 + (lane >> 2);
    const int cbase = col0 + wn * 64 + (lane & 3) * 2;
#pragma unroll
    for (int mt = 0; mt < 2; mt++) {
#pragma unroll
        for (int nt = 0; nt < 8; nt++) {
            const int col = cbase + nt * 8;
            float bx = 0.f, by = 0.f;
            if (p.bias) { bx = p.bias[col]; by = p.bias[col + 1]; }
#pragma unroll
            for (int h = 0; h < 2; h++) {
                const int r = rbase + mt * 16 + h * 8;
                float vx = c[mt][nt][h * 2 + 0] * alpha + bx;
                float vy = c[mt][nt][h * 2 + 1] * alpha + by;
                if (p.relu) { vx = fmaxf(vx, 0.f); vy = fmaxf(vy, 0.f); }
                *reinterpret_cast<float2*>(C + (size_t)r * p.ldc + col) = make_float2(vx, vy);
            }
        }
    }
}

// =============================================================================
// band_att_mma (merged branches, 3-stage pipeline): 64 q x 128 k logits via
// tf32 mma, band softmax -> attb.  smem: A0 A1 A2 B0 B1 B2; S overlays.
// =============================================================================
struct BA2 {
    const float* Q[2]; const float* Km[2]; float* attb[2]; int d[2]; int n;
};

#define BA_ATILE (64 * 36 * 4)    // 9216
#define BA_BTILE (128 * 36 * 4)   // 18432
#define BA_SMEM  (3 * BA_ATILE + 3 * BA_BTILE)  // 82944

__global__ void __launch_bounds__(256)
band_att_mma(BA2 pp)
{
    extern __shared__ char dsm[];
    const int br = blockIdx.y;
    const float* Q   = pp.Q[br];
    const float* Km  = pp.Km[br];
    float* attb      = pp.attb[br];
    const int d      = pp.d[br];
    const int n      = pp.n;

    const int tid  = threadIdx.x;
    const int lane = tid & 31;
    const int wid  = tid >> 5;
    const int wm   = wid & 1;
    const int wn   = wid >> 1;

    const int q0 = blockIdx.x * 64;
    const int jbase = q0 - 32;

    const uint32_t sbase = smem_u32(dsm);
    float* S = reinterpret_cast<float*>(dsm);

    const int larA = tid >> 2;
    const int lacA = (tid & 3) * 8;
    const int larB = tid >> 1;
    const int lacB = (tid & 1) * 16;
    const int jB   = min(max(jbase + larB, 0), n - 1);
    const float* Qg = Q  + (size_t)(q0 + larA) * d + lacA;
    const float* Kg = Km + (size_t)jB * d + lacB;
    const uint32_t a_stw = sbase + ((uint32_t)larA * 36u + (uint32_t)lacA) * 4u;
    const uint32_t b_stw = sbase + 3u * BA_ATILE +
                           ((uint32_t)larB * 36u + (uint32_t)lacB) * 4u;

    const uint32_t a_ld0 = sbase +
        (((uint32_t)(wm * 32 + (lane & 15))) * 36u + ((uint32_t)(lane >> 4)) * 4u) * 4u;
    const uint32_t b_row = (uint32_t)(wn * 32 + (lane & 7) + ((lane & 16) >> 1));
    const uint32_t b_ld0 = sbase + 3u * BA_ATILE +
        (b_row * 36u + (((uint32_t)lane >> 3) & 1u) * 4u) * 4u;

    float c[2][4][4];
#pragma unroll
    for (int mt = 0; mt < 2; mt++)
#pragma unroll
        for (int nt = 0; nt < 4; nt++)
#pragma unroll
            for (int q = 0; q < 4; q++) c[mt][nt][q] = 0.f;

    const int nch = d / 32;

    auto prefetch = [&](int ck, uint32_t aoff, uint32_t boff) {
        const float* qg = Qg + ck * 32;
        const float* kg = Kg + ck * 32;
#pragma unroll
        for (int i = 0; i < 2; i++) cp16(a_stw + aoff + 16u * i, qg + 4 * i);
#pragma unroll
        for (int i = 0; i < 4; i++) cp16(b_stw + boff + 16u * i, kg + 4 * i);
        CP_COMMIT();
    };

    auto compute = [&](uint32_t aoff, uint32_t boff) {
        const uint32_t a_base = a_ld0 + aoff;
        const uint32_t b_base = b_ld0 + boff;
#pragma unroll
        for (int k8 = 0; k8 < 4; k8++) {
            uint32_t a[2][4], b[2][4];
#pragma unroll
            for (int mt = 0; mt < 2; mt++) {
                LDMX4(a[mt][0], a[mt][1], a[mt][2], a[mt][3],
                      a_base + (uint32_t)mt * (16u * 36u * 4u) + (uint32_t)k8 * 32u);
#pragma unroll
                for (int q = 0; q < 4; q++) CVT_INPLACE(a[mt][q]);
            }
#pragma unroll
            for (int pr = 0; pr < 2; pr++) {
                LDMX4(b[pr][0], b[pr][1], b[pr][2], b[pr][3],
                      b_base + (uint32_t)pr * (16u * 36u * 4u) + (uint32_t)k8 * 32u);
#pragma unroll
                for (int q = 0; q < 4; q++) CVT_INPLACE(b[pr][q]);
            }
#pragma unroll
            for (int mt = 0; mt < 2; mt++)
#pragma unroll
                for (int nt = 0; nt < 4; nt++) {
                    const int pr = nt >> 1;
                    if (nt & 1) MMA_TF32(c[mt][nt], a[mt][0], a[mt][1], a[mt][2], a[mt][3],
                                         b[pr][2], b[pr][3]);
                    else        MMA_TF32(c[mt][nt], a[mt][0], a[mt][1], a[mt][2], a[mt][3],
                                         b[pr][0], b[pr][1]);
                }
        }
    };

    prefetch(0, 0u, 0u);
    if (nch > 1) prefetch(1, BA_ATILE, BA_BTILE);

#define BA_ITER(ck, BUF) do { \
        if ((ck) + 1 < nch) CP_WAIT(1); else CP_WAIT(0); \
        __syncthreads(); \
        if ((ck) + 2 < nch) \
            prefetch((ck) + 2, (uint32_t)((((BUF) + 2) % 3) * BA_ATILE), \
                               (uint32_t)((((BUF) + 2) % 3) * BA_BTILE)); \
        compute((uint32_t)((BUF) * BA_ATILE), (uint32_t)((BUF) * BA_BTILE)); \
    } while (0)

    for (int c0 = 0; c0 < nch; c0 += 3) {
        BA_ITER(c0, 0);
        if (c0 + 1 < nch) BA_ITER(c0 + 1, 1);
        if (c0 + 2 < nch) BA_ITER(c0 + 2, 2);
    }
#undef BA_ITER

    // all warps must finish reading stage buffers before S overlays them
    __syncthreads();

    // store logits into S[64][132]
#pragma unroll
    for (int mt = 0; mt < 2; mt++)
#pragma unroll
        for (int nt = 0; nt < 4; nt++)
#pragma unroll
            for (int h = 0; h < 2; h++) {
                const int r = wm * 32 + mt * 16 + (lane >> 2) + h * 8;
                const int cc = wn * 32 + nt * 8 + (lane & 3) * 2;
                S[r * 132 + cc]     = c[mt][nt][h * 2 + 0];
                S[r * 132 + cc + 1] = c[mt][nt][h * 2 + 1];
            }
    __syncthreads();

    // band softmax
    const int i = wid * 8 + (lane >> 2);
    const int sl = lane & 3;
    float vals[10];
    float m = -1e30f;
#pragma unroll
    for (int k = 0; k < 10; k++) {
        const int s = sl + 4 * k;
        float v = -1e30f;
        if (s < BANDW) {
            const int j = q0 + i + s - (APP - 1);
            if (j >= 0 && j < n) v = S[i * 132 + (i + 13 + s)];
        }
        vals[k] = v;
        m = fmaxf(m, v);
    }
    m = fmaxf(m, __shfl_xor_sync(0xffffffffu, m, 1));
    m = fmaxf(m, __shfl_xor_sync(0xffffffffu, m, 2));
    float sum = 0.f;
#pragma unroll
    for (int k = 0; k < 10; k++) {
        const float e = expf(vals[k] - m);
        vals[k] = e;
        sum += e;
    }
    sum += __shfl_xor_sync(0xffffffffu, sum, 1);
    sum += __shfl_xor_sync(0xffffffffu, sum, 2);
    const float inv = 1.f / sum;
#pragma unroll
    for (int k = 0; k < 10; k++) {
        const int s = sl + 4 * k;
        if (s < BANDW)
            attb[(size_t)(q0 + i) * BANDP + s] = vals[k] * inv;
    }
}

// =============================================================================
// band_apply (chunk-parallel): grid (nb, nchunk). 64 outputs x 128 cols per CTA.
// =============================================================================
#define BP_SMEM 62464

__global__ void __launch_bounds__(256)
band_apply_c(const float* __restrict__ attb, const float* __restrict__ V,
             float* __restrict__ Y, int n, int d)
{
    extern __shared__ char dsm[];
    float* ws = reinterpret_cast<float*>(dsm);            // [64][40]
    float* Vs = reinterpret_cast<float*>(dsm + 10240);    // [102][128]

    const int tid = threadIdx.x;
    const int q0 = blockIdx.x * 64;
    const int ch = blockIdx.y;
    const int jbase = q0 - (APP - 1);

    for (int idx = tid; idx < 64 * BANDW; idx += 256) {
        const int i = idx / BANDW;
        const int s = idx - i * BANDW;
        const int j = q0 + i + s - (APP - 1);
        float w = 0.f;
        if (j >= 0 && j < n) w = attb[(size_t)j * BANDP + (38 - s)];
        ws[i * 40 + s] = w;
    }

    for (int idx = tid; idx < 102 * 32; idx += 256) {
        const int row = idx >> 5;
        const int c4  = idx & 31;
        const int j = min(max(jbase + row, 0), n - 1);
        *reinterpret_cast<float4*>(&Vs[row * 128 + c4 * 4]) =
            *reinterpret_cast<const float4*>(V + (size_t)j * d + ch * 128 + c4 * 4);
    }
    __syncthreads();

    const int qg = tid >> 5;
    const int cg = tid & 31;

    float4 acc[8];
#pragma unroll
    for (int q = 0; q < 8; q++) acc[q] = make_float4(0.f, 0.f, 0.f, 0.f);

#pragma unroll
    for (int r = 0; r <= 45; r++) {
        const float4 v4 = *reinterpret_cast<const float4*>(&Vs[(qg * 8 + r) * 128 + cg * 4]);
#pragma unroll
        for (int q = 0; q < 8; q++) {
            const int s = r - q;
            if (s >= 0 && s < BANDW) {
                const float w = ws[(qg * 8 + q) * 40 + s];
                acc[q].x = fmaf(w, v4.x, acc[q].x);
                acc[q].y = fmaf(w, v4.y, acc[q].y);
                acc[q].z = fmaf(w, v4.z, acc[q].z);
                acc[q].w = fmaf(w, v4.w, acc[q].w);
            }
        }
    }
#pragma unroll
    for (int q = 0; q < 8; q++) {
        const int i = q0 + qg * 8 + q;
        *reinterpret_cast<float4*>(Y + (size_t)i * d + ch * 128 + cg * 4) = acc[q];
    }
}

// ---------------- residual + layernorm (merged branches) ---------------------
struct LN2 {
    const float* y[2]; const float* x[2];
    const float* g[2]; const float* b[2];
    float* dst[2]; int d[2]; int stride[2];
};

__global__ void ln_res2(LN2 pp)
{
    __shared__ float sh1[8], sh2[8];
    __shared__ float s_mu, s_rstd;
    const int br = blockIdx.y;
    const float* y = pp.y[br];
    const float* x = pp.x[br];
    const float* g = pp.g[br];
    const float* b = pp.b[br];
    float* dst = pp.dst[br];
    const int d = pp.d[br];
    const int dstride = pp.stride[br];

    const int i = blockIdx.x;
    const int lane = threadIdx.x & 31, wid = threadIdx.x >> 5;

    float sum = 0.f, sq = 0.f;
    for (int c = threadIdx.x; c < d; c += blockDim.x) {
        float v = y[(size_t)i * d + c] + x[(size_t)i * d + c];
        sum += v; sq = fmaf(v, v, sq);
    }
#pragma unroll
    for (int o = 16; o; o >>= 1) {
        sum += __shfl_down_sync(0xffffffffu, sum, o);
        sq  += __shfl_down_sync(0xffffffffu, sq,  o);
    }
    if (lane == 0) { sh1[wid] = sum; sh2[wid] = sq; }
    __syncthreads();
    if (wid == 0) {
        float s = (lane < 8) ? sh1[lane] : 0.f;
        float q = (lane < 8) ? sh2[lane] : 0.f;
#pragma unroll
        for (int o = 4; o; o >>= 1) {
            s += __shfl_down_sync(0xffffffffu, s, o);
            q += __shfl_down_sync(0xffffffffu, q, o);
        }
        if (lane == 0) {
            const float mu = s / d;
            float var = q / d - mu * mu;
            s_mu = mu;
            s_rstd = rsqrtf(var + 1e-6f);
        }
    }
    __syncthreads();
    const float mu = s_mu, rstd = s_rstd;
    for (int c = threadIdx.x; c < d; c += blockDim.x) {
        float v = y[(size_t)i * d + c] + x[(size_t)i * d + c];
        dst[(size_t)i * dstride + c] = (v - mu) * rstd * g[c] + b[c];
    }
}

// ---------------- fused LN(h) + sigmoid head ---------------------------------
__global__ void head_fused(const float* __restrict__ h, const float* __restrict__ g,
                           const float* __restrict__ b, const float* __restrict__ w,
                           const float* __restrict__ kd_b, float* __restrict__ out, int d)
{
    __shared__ float sh[8][5];
    const int i = blockIdx.x;
    const int lane = threadIdx.x & 31, wid = threadIdx.x >> 5;

    float sum = 0.f, sq = 0.f, hgw = 0.f, gw = 0.f, bw = 0.f;
    for (int c = threadIdx.x; c < d; c += blockDim.x) {
        const float hv = h[(size_t)i * d + c];
        const float gc = g[c], bc = b[c], wc = w[c];
        sum += hv; sq = fmaf(hv, hv, sq);
        const float gwc = gc * wc;
        hgw = fmaf(hv, gwc, hgw);
        gw += gwc;
        bw = fmaf(bc, wc, bw);
    }
#pragma unroll
    for (int o = 16; o; o >>= 1) {
        sum += __shfl_down_sync(0xffffffffu, sum, o);
        sq  += __shfl_down_sync(0xffffffffu, sq,  o);
        hgw += __shfl_down_sync(0xffffffffu, hgw, o);
        gw  += __shfl_down_sync(0xffffffffu, gw,  o);
        bw  += __shfl_down_sync(0xffffffffu, bw,  o);
    }
    if (lane == 0) {
        sh[wid][0] = sum; sh[wid][1] = sq; sh[wid][2] = hgw;
        sh[wid][3] = gw;  sh[wid][4] = bw;
    }
    __syncthreads();
    if (wid == 0 && lane == 0) {
        float s = 0.f, q = 0.f, hg = 0.f, gg = 0.f, bb = 0.f;
#pragma unroll
        for (int k = 0; k < 8; k++) {
            s += sh[k][0]; q += sh[k][1]; hg += sh[k][2];
            gg += sh[k][3]; bb += sh[k][4];
        }
        const float mu = s / d;
        const float var = q / d - mu * mu;
        const float rstd = rsqrtf(var + 1e-6f);
        const float sc = rstd * (hg - mu * gg) + bb + kd_b[0];
        out[i] = 1.f / (1.f + expf(-sc));
    }
}

// ---------------- scatter band attention into dense [N, 2N] output ----------
__global__ void scatter_att(const float* __restrict__ attv, const float* __restrict__ atta,
                            float* __restrict__ out, int n)
{
    const int i = blockIdx.x;
    const size_t base = (size_t)n + (size_t)i * 2u * (size_t)n;
    const int j0 = max(i - (APP - 1), 0);
    const int j1 = min(i + (APP - 1), n - 1);
    for (int k = threadIdx.x; k <= j1 - j0; k += blockDim.x) {
        const int j = j0 + k;
        const float av = attv[(size_t)i * BANDP + (j - i + (APP - 1))];
        const float aa = atta[(size_t)i * BANDP + (j - i + (APP - 1))];
        out[base + j]     = av;
        out[base + n + j] = aa;
    }
}

// ---------------- launch ------------------------------------------------------
extern "C" void kernel_launch(void* const* d_in, const int* in_sizes, int n_in,
                              void* d_out, int out_size)
{
    const float* x     = (const float*)d_in[0];
    const float* xa    = (const float*)d_in[1];
    const float* Wk_v  = (const float*)d_in[4];
    const float* Wq_v  = (const float*)d_in[5];
    const float* Wv_v  = (const float*)d_in[6];
    const float* Wo_v  = (const float*)d_in[7];
    const float* Wk_a  = (const float*)d_in[8];
    const float* Wq_a  = (const float*)d_in[9];
    const float* Wv_a  = (const float*)d_in[10];
    const float* Wo_a  = (const float*)d_in[11];
    const float* ka_w  = (const float*)d_in[12];
    const float* ka_b  = (const float*)d_in[13];
    const float* kd_w  = (const float*)d_in[14];
    const float* kd_b  = (const float*)d_in[15];
    const float* ln_y_g  = (const float*)d_in[16];
    const float* ln_y_b  = (const float*)d_in[17];
    const float* ln_ya_g = (const float*)d_in[18];
    const float* ln_ya_b = (const float*)d_in[19];
    const float* ln_ka_g = (const float*)d_in[20];
    const float* ln_ka_b = (const float*)d_in[21];

    const int n = in_sizes[0] / DV;   // 6144

    cudaFuncSetAttribute(tgemm, cudaFuncAttributeMaxDynamicSharedMemorySize, TG_SMEM);
    cudaFuncSetAttribute(band_att_mma, cudaFuncAttributeMaxDynamicSharedMemorySize, BA_SMEM);
    cudaFuncSetAttribute(band_apply_c, cudaFuncAttributeMaxDynamicSharedMemorySize, BP_SMEM);

    float *Kv, *Qv, *Vv, *Yv, *Yov, *Ka, *Qa, *Va, *Ya, *Yoa, *attv, *atta, *ycomb, *h;
    cudaGetSymbolAddress((void**)&Kv,  g_Kv);
    cudaGetSymbolAddress((void**)&Qv,  g_Qv);
    cudaGetSymbolAddress((void**)&Vv,  g_Vv);
    cudaGetSymbolAddress((void**)&Yv,  g_Yv);
    cudaGetSymbolAddress((void**)&Yov, g_Yov);
    cudaGetSymbolAddress((void**)&Ka,  g_Ka);
    cudaGetSymbolAddress((void**)&Qa,  g_Qa);
    cudaGetSymbolAddress((void**)&Va,  g_Va);
    cudaGetSymbolAddress((void**)&Ya,  g_Ya);
    cudaGetSymbolAddress((void**)&Yoa, g_Yoa);
    cudaGetSymbolAddress((void**)&attv, g_attv);
    cudaGetSymbolAddress((void**)&atta, g_atta);
    cudaGetSymbolAddress((void**)&ycomb, g_ycomb);
    cudaGetSymbolAddress((void**)&h,   g_h);

    float* out = (float*)d_out;
    const size_t full_elems = (size_t)n + 2ull * (size_t)n * (size_t)n;
    const size_t clear = ((size_t)out_size >= full_elems) ? full_elems : (size_t)out_size;
    cudaMemsetAsync(out, 0, clear * sizeof(float), 0);

    const int nb = n / 64;   // 96 band blocks

    // --- video QKV (batched z) ---
    {
        TG p; p.A = x;
        p.B0 = Wk_v; p.B1 = Wq_v; p.B2 = Wv_v;
        p.C0 = Kv;   p.C1 = Qv;   p.C2 = Vv;
        p.a0 = 1.f;  p.a1 = 0.06f; p.a2 = 1.f;
        p.bias = nullptr; p.relu = 0;
        p.K = DV; p.lda = DV; p.ldb = DV; p.ldc = DV;
        tgemm<<<dim3(DV / 128, n / 128, 3), 256, TG_SMEM>>>(p);
    }
    // --- audio QKV (batched z) ---
    {
        TG p; p.A = xa;
        p.B0 = Wk_a; p.B1 = Wq_a; p.B2 = Wv_a;
        p.C0 = Ka;   p.C1 = Qa;   p.C2 = Va;
        p.a0 = 1.f;  p.a1 = 0.06f; p.a2 = 1.f;
        p.bias = nullptr; p.relu = 0;
        p.K = DA; p.lda = DA; p.ldb = DA; p.ldc = DA;
        tgemm<<<dim3(DA / 128, n / 128, 3), 256, TG_SMEM>>>(p);
    }

    // --- merged band attention (video + audio) ---
    {
        BA2 p;
        p.Q[0] = Qv; p.Km[0] = Kv; p.attb[0] = attv; p.d[0] = DV;
        p.Q[1] = Qa; p.Km[1] = Ka; p.attb[1] = atta; p.d[1] = DA;
        p.n = n;
        band_att_mma<<<dim3(nb, 2), 256, BA_SMEM>>>(p);
    }

    // --- chunk-parallel band apply ---
    band_apply_c<<<dim3(nb, DV / 128), 256, BP_SMEM>>>(attv, Vv, Yv, n, DV);
    band_apply_c<<<dim3(nb, DA / 128), 256, BP_SMEM>>>(atta, Va, Ya, n, DA);

    // --- video Wo ---
    {
        TG p; p.A = Yv;
        p.B0 = Wo_v; p.B1 = Wo_v; p.B2 = Wo_v;
        p.C0 = Yov;  p.C1 = Yov;  p.C2 = Yov;
        p.a0 = 1.f; p.a1 = 1.f; p.a2 = 1.f;
        p.bias = nullptr; p.relu = 0;
        p.K = DV; p.lda = DV; p.ldb = DV; p.ldc = DV;
        tgemm<<<dim3(DV / 128, n / 128, 1), 256, TG_SMEM>>>(p);
    }
    // --- audio Wo ---
    {
        TG p; p.A = Ya;
        p.B0 = Wo_a; p.B1 = Wo_a; p.B2 = Wo_a;
        p.C0 = Yoa;  p.C1 = Yoa;  p.C2 = Yoa;
        p.a0 = 1.f; p.a1 = 1.f; p.a2 = 1.f;
        p.bias = nullptr; p.relu = 0;
        p.K = DA; p.lda = DA; p.ldb = DA; p.ldc = DA;
        tgemm<<<dim3(DA / 128, n / 128, 1), 256, TG_SMEM>>>(p);
    }

    // --- merged residual LN (video + audio) -> ycomb ---
    {
        LN2 p;
        p.y[0] = Yov; p.x[0] = x;  p.g[0] = ln_y_g;  p.b[0] = ln_y_b;
        p.dst[0] = ycomb;      p.d[0] = DV; p.stride[0] = DC;
        p.y[1] = Yoa; p.x[1] = xa; p.g[1] = ln_ya_g; p.b[1] = ln_ya_b;
        p.dst[1] = ycomb + DV; p.d[1] = DA; p.stride[1] = DC;
        ln_res2<<<dim3(n, 2), 256>>>(p);
    }

    // --- MLP head GEMM ---
    {
        TG p; p.A = ycomb;
        p.B0 = ka_w; p.B1 = ka_w; p.B2 = ka_w;
        p.C0 = h;    p.C1 = h;    p.C2 = h;
        p.a0 = 1.f; p.a1 = 1.f; p.a2 = 1.f;
        p.bias = ka_b; p.relu = 1;
        p.K = DC; p.lda = DC; p.ldb = DC; p.ldc = DH;
        tgemm<<<dim3(DH / 128, n / 128, 1), 256, TG_SMEM>>>(p);
    }

    // --- fused LN + sigmoid head ---
    head_fused<<<n, 256>>>(h, ln_ka_g, ln_ka_b, kd_w, kd_b, out, DH);

    // --- dense attention output ---
    if ((size_t)out_size >= full_elems)
        scatter_att<<<n, 64>>>(attv, atta, out, n);
}

// round 14
// speedup vs baseline: 1.2986x; 1.2986x over previous
#include <cuda_runtime.h>
#include <cstdint>
#include <math.h>

#define NTOK 6144
#define DV   1024
#define DA   128
#define DC   (DV + DA)   // 1152
#define DH   1024
#define APP  20
#define BANDW 39
#define BANDP 40

// ---------------- scratch (static device globals; no allocation) -------------
__device__ float g_Kv [NTOK * DV];
__device__ float g_Qv [NTOK * DV];
__device__ float g_Vv [NTOK * DV];
__device__ float g_Yv [NTOK * DV];
__device__ float g_Yov[NTOK * DV];
__device__ float g_Ka [NTOK * DA];
__device__ float g_Qa [NTOK * DA];
__device__ float g_Va [NTOK * DA];
__device__ float g_Ya [NTOK * DA];
__device__ float g_Yoa[NTOK * DA];
__device__ float g_attv[NTOK * BANDP];
__device__ float g_atta[NTOK * BANDP];
__device__ float g_ycomb[NTOK * DC];
__device__ float g_h  [NTOK * DH];

// ======================= helpers =============================================
__device__ __forceinline__ uint32_t smem_u32(const void* p) {
    uint32_t r;
    asm("{ .reg .u64 t; cvta.to.shared.u64 t, %1; cvt.u32.u64 %0, t; }"
        : "=r"(r) : "l"(p));
    return r;
}

__device__ __forceinline__ uint32_t f2tf32(float x) {
    uint32_t r;
    asm("cvt.rna.tf32.f32 %0, %1;" : "=r"(r) : "f"(x));
    return r;
}

__device__ __forceinline__ void cp16(uint32_t dst, const void* src) {
    asm volatile("cp.async.ca.shared.global [%0], [%1], 16;" :: "r"(dst), "l"(src));
}
#define CP_COMMIT() asm volatile("cp.async.commit_group;" ::: "memory")
#define CP_WAIT(n)  asm volatile("cp.async.wait_group %0;" :: "n"(n) : "memory")

#define LDMX4(r0, r1, r2, r3, addr) \
    asm volatile("ldmatrix.sync.aligned.m8n8.x4.shared.b16 {%0,%1,%2,%3}, [%4];" \
                 : "=r"(r0), "=r"(r1), "=r"(r2), "=r"(r3) : "r"(addr))

#define MMA_TF32(c, a0, a1, a2, a3, b0, b1) \
    asm volatile("mma.sync.aligned.m16n8k8.row.col.f32.tf32.tf32.f32 " \
                 "{%0,%1,%2,%3}, {%4,%5,%6,%7}, {%8,%9}, {%0,%1,%2,%3};" \
                 : "+f"((c)[0]), "+f"((c)[1]), "+f"((c)[2]), "+f"((c)[3]) \
                 : "r"(a0), "r"(a1), "r"(a2), "r"(a3), "r"(b0), "r"(b1))

#define CVT_INPLACE(r) (r) = f2tf32(__uint_as_float(r))

// =============================================================================
// tgemm: C[z] = alpha[z] * A * B[z]^T (+bias)(relu), tf32 mma.
// 2-stage cp.async (73.7KB smem -> 2 CTAs/SM), ONE sync per chunk:
//   wait -> sync -> prefetch(buf^1) -> compute(buf)
// CTA tile 128x128, BK=32, 8 warps (4M x 2N). smem: A0 A1 B0 B1, each 128x36.
// =============================================================================
struct TG {
    const float* A;
    const float *B0, *B1, *B2;
    float *C0, *C1, *C2;
    float a0, a1, a2;
    const float* bias;
    int relu;
    int K, lda, ldb, ldc;
};

#define TILE_BYTES (128 * 36 * 4)           // 18432
#define TG_SMEM    (4 * TILE_BYTES)         // 73728

__global__ void __launch_bounds__(256)
tgemm(TG p)
{
    extern __shared__ char dsm[];
    const int tid  = threadIdx.x;
    const int lane = tid & 31;
    const int wid  = tid >> 5;
    const int wm   = wid & 3;
    const int wn   = wid >> 2;

    const int row0 = blockIdx.y * 128;
    const int col0 = blockIdx.x * 128;
    const int z = blockIdx.z;
    const float* B = (z == 0) ? p.B0 : (z == 1) ? p.B1 : p.B2;
    float*       C = (z == 0) ? p.C0 : (z == 1) ? p.C1 : p.C2;
    const float alpha = (z == 0) ? p.a0 : (z == 1) ? p.a1 : p.a2;

    const uint32_t sbase = smem_u32(dsm);

    const int lrow = tid >> 1;
    const int lcol = (tid & 1) * 16;
    const float* Ag = p.A + (size_t)(row0 + lrow) * p.lda + lcol;
    const float* Bg = B   + (size_t)(col0 + lrow) * p.ldb + lcol;
    const uint32_t a_stw = sbase + ((uint32_t)lrow * 36u + (uint32_t)lcol) * 4u;
    const uint32_t b_stw = a_stw + 2u * TILE_BYTES;

    const uint32_t a_ld0 = sbase +
        (((uint32_t)(wm * 32 + (lane & 15))) * 36u + ((uint32_t)(lane >> 4)) * 4u) * 4u;
    const uint32_t b_row = (uint32_t)(wn * 64 + (lane & 7) + ((lane & 16) >> 1));
    const uint32_t b_ld0 = sbase + 2u * TILE_BYTES +
        (b_row * 36u + (((uint32_t)lane >> 3) & 1u) * 4u) * 4u;

    float c[2][8][4];
#pragma unroll
    for (int mt = 0; mt < 2; mt++)
#pragma unroll
        for (int nt = 0; nt < 8; nt++)
#pragma unroll
            for (int q = 0; q < 4; q++) c[mt][nt][q] = 0.f;

    const int nch = p.K / 32;

    // prologue: chunk 0 -> buf 0
#pragma unroll
    for (int i = 0; i < 4; i++) {
        cp16(a_stw + 16u * i, Ag + 4 * i);
        cp16(b_stw + 16u * i, Bg + 4 * i);
    }
    CP_COMMIT();

    for (int ck = 0; ck < nch; ++ck) {
        const int buf = ck & 1;
        CP_WAIT(0);
        __syncthreads();
        if (ck + 1 < nch) {
            const uint32_t off = (uint32_t)(buf ^ 1) * TILE_BYTES;
            const float* ag = Ag + (ck + 1) * 32;
            const float* bg = Bg + (ck + 1) * 32;
#pragma unroll
            for (int i = 0; i < 4; i++) {
                cp16(a_stw + off + 16u * i, ag + 4 * i);
                cp16(b_stw + off + 16u * i, bg + 4 * i);
            }
            CP_COMMIT();
        }

        const uint32_t a_base = a_ld0 + (uint32_t)buf * TILE_BYTES;
        const uint32_t b_base = b_ld0 + (uint32_t)buf * TILE_BYTES;
#pragma unroll
        for (int k8 = 0; k8 < 4; k8++) {
            uint32_t a[2][4], b[4][4];
#pragma unroll
            for (int mt = 0; mt < 2; mt++) {
                LDMX4(a[mt][0], a[mt][1], a[mt][2], a[mt][3],
                      a_base + (uint32_t)mt * (16u * 36u * 4u) + (uint32_t)k8 * 32u);
#pragma unroll
                for (int q = 0; q < 4; q++) CVT_INPLACE(a[mt][q]);
            }
#pragma unroll
            for (int pr = 0; pr < 4; pr++) {
                LDMX4(b[pr][0], b[pr][1], b[pr][2], b[pr][3],
                      b_base + (uint32_t)pr * (16u * 36u * 4u) + (uint32_t)k8 * 32u);
#pragma unroll
                for (int q = 0; q < 4; q++) CVT_INPLACE(b[pr][q]);
            }
#pragma unroll
            for (int mt = 0; mt < 2; mt++)
#pragma unroll
                for (int nt = 0; nt < 8; nt++) {
                    const int pr = nt >> 1;
                    if (nt & 1) MMA_TF32(c[mt][nt], a[mt][0], a[mt][1], a[mt][2], a[mt][3],
                                         b[pr][2], b[pr][3]);
                    else        MMA_TF32(c[mt][nt], a[mt][0], a[mt][1], a[mt][2], a[mt][3],
                                         b[pr][0], b[pr][1]);
                }
        }
    }

    const int rbase = row0 + wm * 32 + (lane >> 2);
    const int cbase = col0 + wn * 64 + (lane & 3) * 2;
#pragma unroll
    for (int mt = 0; mt < 2; mt++) {
#pragma unroll
        for (int nt = 0; nt < 8; nt++) {
            const int col = cbase + nt * 8;
            float bx = 0.f, by = 0.f;
            if (p.bias) { bx = p.bias[col]; by = p.bias[col + 1]; }
#pragma unroll
            for (int h = 0; h < 2; h++) {
                const int r = rbase + mt * 16 + h * 8;
                float vx = c[mt][nt][h * 2 + 0] * alpha + bx;
                float vy = c[mt][nt][h * 2 + 1] * alpha + by;
                if (p.relu) { vx = fmaxf(vx, 0.f); vy = fmaxf(vy, 0.f); }
                *reinterpret_cast<float2*>(C + (size_t)r * p.ldc + col) = make_float2(vx, vy);
            }
        }
    }
}

// =============================================================================
// band_att_mma (merged branches, 2-stage, ONE sync per chunk):
// 64 q x 128 k logits via tf32 mma, band softmax -> attb.
// =============================================================================
struct BA2 {
    const float* Q[2]; const float* Km[2]; float* attb[2]; int d[2]; int n;
};

#define BA_ATILE (64 * 36 * 4)    // 9216
#define BA_BTILE (128 * 36 * 4)   // 18432
#define BA_SMEM  (2 * BA_ATILE + 2 * BA_BTILE)  // 55296

__global__ void __launch_bounds__(256)
band_att_mma(BA2 pp)
{
    extern __shared__ char dsm[];
    const int br = blockIdx.y;
    const float* Q   = pp.Q[br];
    const float* Km  = pp.Km[br];
    float* attb      = pp.attb[br];
    const int d      = pp.d[br];
    const int n      = pp.n;

    const int tid  = threadIdx.x;
    const int lane = tid & 31;
    const int wid  = tid >> 5;
    const int wm   = wid & 1;
    const int wn   = wid >> 1;

    const int q0 = blockIdx.x * 64;
    const int jbase = q0 - 32;

    const uint32_t sbase = smem_u32(dsm);
    float* S = reinterpret_cast<float*>(dsm);

    const int larA = tid >> 2;
    const int lacA = (tid & 3) * 8;
    const int larB = tid >> 1;
    const int lacB = (tid & 1) * 16;
    const int jB   = min(max(jbase + larB, 0), n - 1);
    const float* Qg = Q  + (size_t)(q0 + larA) * d + lacA;
    const float* Kg = Km + (size_t)jB * d + lacB;
    const uint32_t a_stw = sbase + ((uint32_t)larA * 36u + (uint32_t)lacA) * 4u;
    const uint32_t b_stw = sbase + 2u * BA_ATILE +
                           ((uint32_t)larB * 36u + (uint32_t)lacB) * 4u;

    const uint32_t a_ld0 = sbase +
        (((uint32_t)(wm * 32 + (lane & 15))) * 36u + ((uint32_t)(lane >> 4)) * 4u) * 4u;
    const uint32_t b_row = (uint32_t)(wn * 32 + (lane & 7) + ((lane & 16) >> 1));
    const uint32_t b_ld0 = sbase + 2u * BA_ATILE +
        (b_row * 36u + (((uint32_t)lane >> 3) & 1u) * 4u) * 4u;

    float c[2][4][4];
#pragma unroll
    for (int mt = 0; mt < 2; mt++)
#pragma unroll
        for (int nt = 0; nt < 4; nt++)
#pragma unroll
            for (int q = 0; q < 4; q++) c[mt][nt][q] = 0.f;

    const int nch = d / 32;

#pragma unroll
    for (int i = 0; i < 2; i++) cp16(a_stw + 16u * i, Qg + 4 * i);
#pragma unroll
    for (int i = 0; i < 4; i++) cp16(b_stw + 16u * i, Kg + 4 * i);
    CP_COMMIT();

    for (int ck = 0; ck < nch; ++ck) {
        const int buf = ck & 1;
        CP_WAIT(0);
        __syncthreads();
        if (ck + 1 < nch) {
            const float* qg = Qg + (ck + 1) * 32;
            const float* kg = Kg + (ck + 1) * 32;
            const uint32_t ao = (uint32_t)(buf ^ 1) * BA_ATILE;
            const uint32_t bo = (uint32_t)(buf ^ 1) * BA_BTILE;
#pragma unroll
            for (int i = 0; i < 2; i++) cp16(a_stw + ao + 16u * i, qg + 4 * i);
#pragma unroll
            for (int i = 0; i < 4; i++) cp16(b_stw + bo + 16u * i, kg + 4 * i);
            CP_COMMIT();
        }

        const uint32_t a_base = a_ld0 + (uint32_t)buf * BA_ATILE;
        const uint32_t b_base = b_ld0 + (uint32_t)buf * BA_BTILE;
#pragma unroll
        for (int k8 = 0; k8 < 4; k8++) {
            uint32_t a[2][4], b[2][4];
#pragma unroll
            for (int mt = 0; mt < 2; mt++) {
                LDMX4(a[mt][0], a[mt][1], a[mt][2], a[mt][3],
                      a_base + (uint32_t)mt * (16u * 36u * 4u) + (uint32_t)k8 * 32u);
#pragma unroll
                for (int q = 0; q < 4; q++) CVT_INPLACE(a[mt][q]);
            }
#pragma unroll
            for (int pr = 0; pr < 2; pr++) {
                LDMX4(b[pr][0], b[pr][1], b[pr][2], b[pr][3],
                      b_base + (uint32_t)pr * (16u * 36u * 4u) + (uint32_t)k8 * 32u);
#pragma unroll
                for (int q = 0; q < 4; q++) CVT_INPLACE(b[pr][q]);
            }
#pragma unroll
            for (int mt = 0; mt < 2; mt++)
#pragma unroll
                for (int nt = 0; nt < 4; nt++) {
                    const int pr = nt >> 1;
                    if (nt & 1) MMA_TF32(c[mt][nt], a[mt][0], a[mt][1], a[mt][2], a[mt][3],
                                         b[pr][2], b[pr][3]);
                    else        MMA_TF32(c[mt][nt], a[mt][0], a[mt][1], a[mt][2], a[mt][3],
                                         b[pr][0], b[pr][1]);
                }
        }
    }

    // all warps must finish reading stage buffers before S overlays them
    __syncthreads();

    // store logits into S[64][132]
#pragma unroll
    for (int mt = 0; mt < 2; mt++)
#pragma unroll
        for (int nt = 0; nt < 4; nt++)
#pragma unroll
            for (int h = 0; h < 2; h++) {
                const int r = wm * 32 + mt * 16 + (lane >> 2) + h * 8;
                const int cc = wn * 32 + nt * 8 + (lane & 3) * 2;
                S[r * 132 + cc]     = c[mt][nt][h * 2 + 0];
                S[r * 132 + cc + 1] = c[mt][nt][h * 2 + 1];
            }
    __syncthreads();

    // band softmax
    const int i = wid * 8 + (lane >> 2);
    const int sl = lane & 3;
    float vals[10];
    float m = -1e30f;
#pragma unroll
    for (int k = 0; k < 10; k++) {
        const int s = sl + 4 * k;
        float v = -1e30f;
        if (s < BANDW) {
            const int j = q0 + i + s - (APP - 1);
            if (j >= 0 && j < n) v = S[i * 132 + (i + 13 + s)];
        }
        vals[k] = v;
        m = fmaxf(m, v);
    }
    m = fmaxf(m, __shfl_xor_sync(0xffffffffu, m, 1));
    m = fmaxf(m, __shfl_xor_sync(0xffffffffu, m, 2));
    float sum = 0.f;
#pragma unroll
    for (int k = 0; k < 10; k++) {
        const float e = expf(vals[k] - m);
        vals[k] = e;
        sum += e;
    }
    sum += __shfl_xor_sync(0xffffffffu, sum, 1);
    sum += __shfl_xor_sync(0xffffffffu, sum, 2);
    const float inv = 1.f / sum;
#pragma unroll
    for (int k = 0; k < 10; k++) {
        const int s = sl + 4 * k;
        if (s < BANDW)
            attb[(size_t)(q0 + i) * BANDP + s] = vals[k] * inv;
    }
}

// =============================================================================
// band_apply (chunk-parallel): grid (nb, nchunk). 64 outputs x 128 cols per CTA.
// =============================================================================
#define BP_SMEM 62464

__global__ void __launch_bounds__(256)
band_apply_c(const float* __restrict__ attb, const float* __restrict__ V,
             float* __restrict__ Y, int n, int d)
{
    extern __shared__ char dsm[];
    float* ws = reinterpret_cast<float*>(dsm);            // [64][40]
    float* Vs = reinterpret_cast<float*>(dsm + 10240);    // [102][128]

    const int tid = threadIdx.x;
    const int q0 = blockIdx.x * 64;
    const int ch = blockIdx.y;
    const int jbase = q0 - (APP - 1);

    for (int idx = tid; idx < 64 * BANDW; idx += 256) {
        const int i = idx / BANDW;
        const int s = idx - i * BANDW;
        const int j = q0 + i + s - (APP - 1);
        float w = 0.f;
        if (j >= 0 && j < n) w = attb[(size_t)j * BANDP + (38 - s)];
        ws[i * 40 + s] = w;
    }

    for (int idx = tid; idx < 102 * 32; idx += 256) {
        const int row = idx >> 5;
        const int c4  = idx & 31;
        const int j = min(max(jbase + row, 0), n - 1);
        *reinterpret_cast<float4*>(&Vs[row * 128 + c4 * 4]) =
            *reinterpret_cast<const float4*>(V + (size_t)j * d + ch * 128 + c4 * 4);
    }
    __syncthreads();

    const int qg = tid >> 5;
    const int cg = tid & 31;

    float4 acc[8];
#pragma unroll
    for (int q = 0; q < 8; q++) acc[q] = make_float4(0.f, 0.f, 0.f, 0.f);

#pragma unroll
    for (int r = 0; r <= 45; r++) {
        const float4 v4 = *reinterpret_cast<const float4*>(&Vs[(qg * 8 + r) * 128 + cg * 4]);
#pragma unroll
        for (int q = 0; q < 8; q++) {
            const int s = r - q;
            if (s >= 0 && s < BANDW) {
                const float w = ws[(qg * 8 + q) * 40 + s];
                acc[q].x = fmaf(w, v4.x, acc[q].x);
                acc[q].y = fmaf(w, v4.y, acc[q].y);
                acc[q].z = fmaf(w, v4.z, acc[q].z);
                acc[q].w = fmaf(w, v4.w, acc[q].w);
            }
        }
    }
#pragma unroll
    for (int q = 0; q < 8; q++) {
        const int i = q0 + qg * 8 + q;
        *reinterpret_cast<float4*>(Y + (size_t)i * d + ch * 128 + cg * 4) = acc[q];
    }
}

// ---------------- residual + layernorm (merged branches) ---------------------
struct LN2 {
    const float* y[2]; const float* x[2];
    const float* g[2]; const float* b[2];
    float* dst[2]; int d[2]; int stride[2];
};

__global__ void ln_res2(LN2 pp)
{
    __shared__ float sh1[8], sh2[8];
    __shared__ float s_mu, s_rstd;
    const int br = blockIdx.y;
    const float* y = pp.y[br];
    const float* x = pp.x[br];
    const float* g = pp.g[br];
    const float* b = pp.b[br];
    float* dst = pp.dst[br];
    const int d = pp.d[br];
    const int dstride = pp.stride[br];

    const int i = blockIdx.x;
    const int lane = threadIdx.x & 31, wid = threadIdx.x >> 5;

    float sum = 0.f, sq = 0.f;
    for (int c = threadIdx.x; c < d; c += blockDim.x) {
        float v = y[(size_t)i * d + c] + x[(size_t)i * d + c];
        sum += v; sq = fmaf(v, v, sq);
    }
#pragma unroll
    for (int o = 16; o; o >>= 1) {
        sum += __shfl_down_sync(0xffffffffu, sum, o);
        sq  += __shfl_down_sync(0xffffffffu, sq,  o);
    }
    if (lane == 0) { sh1[wid] = sum; sh2[wid] = sq; }
    __syncthreads();
    if (wid == 0) {
        float s = (lane < 8) ? sh1[lane] : 0.f;
        float q = (lane < 8) ? sh2[lane] : 0.f;
#pragma unroll
        for (int o = 4; o; o >>= 1) {
            s += __shfl_down_sync(0xffffffffu, s, o);
            q += __shfl_down_sync(0xffffffffu, q, o);
        }
        if (lane == 0) {
            const float mu = s / d;
            float var = q / d - mu * mu;
            s_mu = mu;
            s_rstd = rsqrtf(var + 1e-6f);
        }
    }
    __syncthreads();
    const float mu = s_mu, rstd = s_rstd;
    for (int c = threadIdx.x; c < d; c += blockDim.x) {
        float v = y[(size_t)i * d + c] + x[(size_t)i * d + c];
        dst[(size_t)i * dstride + c] = (v - mu) * rstd * g[c] + b[c];
    }
}

// ---------------- fused LN(h) + sigmoid head ---------------------------------
__global__ void head_fused(const float* __restrict__ h, const float* __restrict__ g,
                           const float* __restrict__ b, const float* __restrict__ w,
                           const float* __restrict__ kd_b, float* __restrict__ out, int d)
{
    __shared__ float sh[8][5];
    const int i = blockIdx.x;
    const int lane = threadIdx.x & 31, wid = threadIdx.x >> 5;

    float sum = 0.f, sq = 0.f, hgw = 0.f, gw = 0.f, bw = 0.f;
    for (int c = threadIdx.x; c < d; c += blockDim.x) {
        const float hv = h[(size_t)i * d + c];
        const float gc = g[c], bc = b[c], wc = w[c];
        sum += hv; sq = fmaf(hv, hv, sq);
        const float gwc = gc * wc;
        hgw = fmaf(hv, gwc, hgw);
        gw += gwc;
        bw = fmaf(bc, wc, bw);
    }
#pragma unroll
    for (int o = 16; o; o >>= 1) {
        sum += __shfl_down_sync(0xffffffffu, sum, o);
        sq  += __shfl_down_sync(0xffffffffu, sq,  o);
        hgw += __shfl_down_sync(0xffffffffu, hgw, o);
        gw  += __shfl_down_sync(0xffffffffu, gw,  o);
        bw  += __shfl_down_sync(0xffffffffu, bw,  o);
    }
    if (lane == 0) {
        sh[wid][0] = sum; sh[wid][1] = sq; sh[wid][2] = hgw;
        sh[wid][3] = gw;  sh[wid][4] = bw;
    }
    __syncthreads();
    if (wid == 0 && lane == 0) {
        float s = 0.f, q = 0.f, hg = 0.f, gg = 0.f, bb = 0.f;
#pragma unroll
        for (int k = 0; k < 8; k++) {
            s += sh[k][0]; q += sh[k][1]; hg += sh[k][2];
            gg += sh[k][3]; bb += sh[k][4];
        }
        const float mu = s / d;
        const float var = q / d - mu * mu;
        const float rstd = rsqrtf(var + 1e-6f);
        const float sc = rstd * (hg - mu * gg) + bb + kd_b[0];
        out[i] = 1.f / (1.f + expf(-sc));
    }
}

// ---------------- scatter band attention into dense [N, 2N] output ----------
__global__ void scatter_att(const float* __restrict__ attv, const float* __restrict__ atta,
                            float* __restrict__ out, int n)
{
    const int i = blockIdx.x;
    const size_t base = (size_t)n + (size_t)i * 2u * (size_t)n;
    const int j0 = max(i - (APP - 1), 0);
    const int j1 = min(i + (APP - 1), n - 1);
    for (int k = threadIdx.x; k <= j1 - j0; k += blockDim.x) {
        const int j = j0 + k;
        const float av = attv[(size_t)i * BANDP + (j - i + (APP - 1))];
        const float aa = atta[(size_t)i * BANDP + (j - i + (APP - 1))];
        out[base + j]     = av;
        out[base + n + j] = aa;
    }
}

// ---------------- launch ------------------------------------------------------
extern "C" void kernel_launch(void* const* d_in, const int* in_sizes, int n_in,
                              void* d_out, int out_size)
{
    const float* x     = (const float*)d_in[0];
    const float* xa    = (const float*)d_in[1];
    const float* Wk_v  = (const float*)d_in[4];
    const float* Wq_v  = (const float*)d_in[5];
    const float* Wv_v  = (const float*)d_in[6];
    const float* Wo_v  = (const float*)d_in[7];
    const float* Wk_a  = (const float*)d_in[8];
    const float* Wq_a  = (const float*)d_in[9];
    const float* Wv_a  = (const float*)d_in[10];
    const float* Wo_a  = (const float*)d_in[11];
    const float* ka_w  = (const float*)d_in[12];
    const float* ka_b  = (const float*)d_in[13];
    const float* kd_w  = (const float*)d_in[14];
    const float* kd_b  = (const float*)d_in[15];
    const float* ln_y_g  = (const float*)d_in[16];
    const float* ln_y_b  = (const float*)d_in[17];
    const float* ln_ya_g = (const float*)d_in[18];
    const float* ln_ya_b = (const float*)d_in[19];
    const float* ln_ka_g = (const float*)d_in[20];
    const float* ln_ka_b = (const float*)d_in[21];

    const int n = in_sizes[0] / DV;   // 6144

    cudaFuncSetAttribute(tgemm, cudaFuncAttributeMaxDynamicSharedMemorySize, TG_SMEM);
    cudaFuncSetAttribute(band_att_mma, cudaFuncAttributeMaxDynamicSharedMemorySize, BA_SMEM);
    cudaFuncSetAttribute(band_apply_c, cudaFuncAttributeMaxDynamicSharedMemorySize, BP_SMEM);

    float *Kv, *Qv, *Vv, *Yv, *Yov, *Ka, *Qa, *Va, *Ya, *Yoa, *attv, *atta, *ycomb, *h;
    cudaGetSymbolAddress((void**)&Kv,  g_Kv);
    cudaGetSymbolAddress((void**)&Qv,  g_Qv);
    cudaGetSymbolAddress((void**)&Vv,  g_Vv);
    cudaGetSymbolAddress((void**)&Yv,  g_Yv);
    cudaGetSymbolAddress((void**)&Yov, g_Yov);
    cudaGetSymbolAddress((void**)&Ka,  g_Ka);
    cudaGetSymbolAddress((void**)&Qa,  g_Qa);
    cudaGetSymbolAddress((void**)&Va,  g_Va);
    cudaGetSymbolAddress((void**)&Ya,  g_Ya);
    cudaGetSymbolAddress((void**)&Yoa, g_Yoa);
    cudaGetSymbolAddress((void**)&attv, g_attv);
    cudaGetSymbolAddress((void**)&atta, g_atta);
    cudaGetSymbolAddress((void**)&ycomb, g_ycomb);
    cudaGetSymbolAddress((void**)&h,   g_h);

    float* out = (float*)d_out;
    const size_t full_elems = (size_t)n + 2ull * (size_t)n * (size_t)n;
    const size_t clear = ((size_t)out_size >= full_elems) ? full_elems : (size_t)out_size;
    cudaMemsetAsync(out, 0, clear * sizeof(float), 0);

    const int nb = n / 64;   // 96 band blocks

    // --- video QKV (batched z) ---
    {
        TG p; p.A = x;
        p.B0 = Wk_v; p.B1 = Wq_v; p.B2 = Wv_v;
        p.C0 = Kv;   p.C1 = Qv;   p.C2 = Vv;
        p.a0 = 1.f;  p.a1 = 0.06f; p.a2 = 1.f;
        p.bias = nullptr; p.relu = 0;
        p.K = DV; p.lda = DV; p.ldb = DV; p.ldc = DV;
        tgemm<<<dim3(DV / 128, n / 128, 3), 256, TG_SMEM>>>(p);
    }
    // --- audio QKV (batched z) ---
    {
        TG p; p.A = xa;
        p.B0 = Wk_a; p.B1 = Wq_a; p.B2 = Wv_a;
        p.C0 = Ka;   p.C1 = Qa;   p.C2 = Va;
        p.a0 = 1.f;  p.a1 = 0.06f; p.a2 = 1.f;
        p.bias = nullptr; p.relu = 0;
        p.K = DA; p.lda = DA; p.ldb = DA; p.ldc = DA;
        tgemm<<<dim3(DA / 128, n / 128, 3), 256, TG_SMEM>>>(p);
    }

    // --- merged band attention (video + audio) ---
    {
        BA2 p;
        p.Q[0] = Qv; p.Km[0] = Kv; p.attb[0] = attv; p.d[0] = DV;
        p.Q[1] = Qa; p.Km[1] = Ka; p.attb[1] = atta; p.d[1] = DA;
        p.n = n;
        band_att_mma<<<dim3(nb, 2), 256, BA_SMEM>>>(p);
    }

    // --- chunk-parallel band apply ---
    band_apply_c<<<dim3(nb, DV / 128), 256, BP_SMEM>>>(attv, Vv, Yv, n, DV);
    band_apply_c<<<dim3(nb, DA / 128), 256, BP_SMEM>>>(atta, Va, Ya, n, DA);

    // --- video Wo ---
    {
        TG p; p.A = Yv;
        p.B0 = Wo_v; p.B1 = Wo_v; p.B2 = Wo_v;
        p.C0 = Yov;  p.C1 = Yov;  p.C2 = Yov;
        p.a0 = 1.f; p.a1 = 1.f; p.a2 = 1.f;
        p.bias = nullptr; p.relu = 0;
        p.K = DV; p.lda = DV; p.ldb = DV; p.ldc = DV;
        tgemm<<<dim3(DV / 128, n / 128, 1), 256, TG_SMEM>>>(p);
    }
    // --- audio Wo ---
    {
        TG p; p.A = Ya;
        p.B0 = Wo_a; p.B1 = Wo_a; p.B2 = Wo_a;
        p.C0 = Yoa;  p.C1 = Yoa;  p.C2 = Yoa;
        p.a0 = 1.f; p.a1 = 1.f; p.a2 = 1.f;
        p.bias = nullptr; p.relu = 0;
        p.K = DA; p.lda = DA; p.ldb = DA; p.ldc = DA;
        tgemm<<<dim3(DA / 128, n / 128, 1), 256, TG_SMEM>>>(p);
    }

    // --- merged residual LN (video + audio) -> ycomb ---
    {
        LN2 p;
        p.y[0] = Yov; p.x[0] = x;  p.g[0] = ln_y_g;  p.b[0] = ln_y_b;
        p.dst[0] = ycomb;      p.d[0] = DV; p.stride[0] = DC;
        p.y[1] = Yoa; p.x[1] = xa; p.g[1] = ln_ya_g; p.b[1] = ln_ya_b;
        p.dst[1] = ycomb + DV; p.d[1] = DA; p.stride[1] = DC;
        ln_res2<<<dim3(n, 2), 256>>>(p);
    }

    // --- MLP head GEMM ---
    {
        TG p; p.A = ycomb;
        p.B0 = ka_w; p.B1 = ka_w; p.B2 = ka_w;
        p.C0 = h;    p.C1 = h;    p.C2 = h;
        p.a0 = 1.f; p.a1 = 1.f; p.a2 = 1.f;
        p.bias = ka_b; p.relu = 1;
        p.K = DC; p.lda = DC; p.ldb = DC; p.ldc = DH;
        tgemm<<<dim3(DH / 128, n / 128, 1), 256, TG_SMEM>>>(p);
    }

    // --- fused LN + sigmoid head ---
    head_fused<<<n, 256>>>(h, ln_ka_g, ln_ka_b, kd_w, kd_b, out, DH);

    // --- dense attention output ---
    if ((size_t)out_size >= full_elems)
        scatter_att<<<n, 64>>>(attv, atta, out, n);
}

// round 16
// speedup vs baseline: 1.3583x; 1.0459x over previous
#include <cuda_runtime.h>
#include <cstdint>
#include <math.h>

#define NTOK 6144
#define DV   1024
#define DA   128
#define DC   (DV + DA)   // 1152
#define DH   1024
#define APP  20
#define BANDW 39
#define BANDP 40

// ---------------- scratch (static device globals; no allocation) -------------
__device__ float g_Kv [NTOK * DV];
__device__ float g_Qv [NTOK * DV];
__device__ float g_Vv [NTOK * DV];
__device__ float g_Yv [NTOK * DV];
__device__ float g_Yov[NTOK * DV];
__device__ float g_Ka [NTOK * DA];
__device__ float g_Qa [NTOK * DA];
__device__ float g_Va [NTOK * DA];
__device__ float g_Ya [NTOK * DA];
__device__ float g_Yoa[NTOK * DA];
__device__ float g_attv[NTOK * BANDP];
__device__ float g_atta[NTOK * BANDP];
__device__ float g_ycomb[NTOK * DC];
__device__ float g_h  [NTOK * DH];

// ======================= helpers =============================================
__device__ __forceinline__ uint32_t smem_u32(const void* p) {
    uint32_t r;
    asm("{ .reg .u64 t; cvta.to.shared.u64 t, %1; cvt.u32.u64 %0, t; }"
        : "=r"(r) : "l"(p));
    return r;
}

__device__ __forceinline__ uint32_t f2tf32(float x) {
    uint32_t r;
    asm("cvt.rna.tf32.f32 %0, %1;" : "=r"(r) : "f"(x));
    return r;
}

__device__ __forceinline__ void cp16(uint32_t dst, const void* src) {
    asm volatile("cp.async.ca.shared.global [%0], [%1], 16;" :: "r"(dst), "l"(src));
}
#define CP_COMMIT() asm volatile("cp.async.commit_group;" ::: "memory")
#define CP_WAIT(n)  asm volatile("cp.async.wait_group %0;" :: "n"(n) : "memory")

#define LDMX4(r0, r1, r2, r3, addr) \
    asm volatile("ldmatrix.sync.aligned.m8n8.x4.shared.b16 {%0,%1,%2,%3}, [%4];" \
                 : "=r"(r0), "=r"(r1), "=r"(r2), "=r"(r3) : "r"(addr))

#define MMA_TF32(c, a0, a1, a2, a3, b0, b1) \
    asm volatile("mma.sync.aligned.m16n8k8.row.col.f32.tf32.tf32.f32 " \
                 "{%0,%1,%2,%3}, {%4,%5,%6,%7}, {%8,%9}, {%0,%1,%2,%3};" \
                 : "+f"((c)[0]), "+f"((c)[1]), "+f"((c)[2]), "+f"((c)[3]) \
                 : "r"(a0), "r"(a1), "r"(a2), "r"(a3), "r"(b0), "r"(b1))

#define CVT_INPLACE(r) (r) = f2tf32(__uint_as_float(r))

// =============================================================================
// tgemm: C[z] = alpha[z] * A * B[z]^T (+bias)(relu), tf32 mma.
// R10 pipeline skeleton (prefetch -> wait(1) -> sync -> compute -> sync)
// + fragment double-buffering across k8 steps.
// CTA tile 128x128, BK=32, 8 warps (4M x 2N). smem: A0 A1 B0 B1, each 128x36.
// =============================================================================
struct TG {
    const float* A;
    const float *B0, *B1, *B2;
    float *C0, *C1, *C2;
    float a0, a1, a2;
    const float* bias;
    int relu;
    int K, lda, ldb, ldc;
};

#define TILE_BYTES (128 * 36 * 4)           // 18432
#define TG_SMEM    (4 * TILE_BYTES)         // 73728

__global__ void __launch_bounds__(256, 2)
tgemm(TG p)
{
    extern __shared__ char dsm[];
    const int tid  = threadIdx.x;
    const int lane = tid & 31;
    const int wid  = tid >> 5;
    const int wm   = wid & 3;
    const int wn   = wid >> 2;

    const int row0 = blockIdx.y * 128;
    const int col0 = blockIdx.x * 128;
    const int z = blockIdx.z;
    const float* B = (z == 0) ? p.B0 : (z == 1) ? p.B1 : p.B2;
    float*       C = (z == 0) ? p.C0 : (z == 1) ? p.C1 : p.C2;
    const float alpha = (z == 0) ? p.a0 : (z == 1) ? p.a1 : p.a2;

    const uint32_t sbase = smem_u32(dsm);

    const int lrow = tid >> 1;
    const int lcol = (tid & 1) * 16;
    const float* Ag = p.A + (size_t)(row0 + lrow) * p.lda + lcol;
    const float* Bg = B   + (size_t)(col0 + lrow) * p.ldb + lcol;
    const uint32_t a_stw = sbase + ((uint32_t)lrow * 36u + (uint32_t)lcol) * 4u;
    const uint32_t b_stw = a_stw + 2u * TILE_BYTES;

    const uint32_t a_ld0 = sbase +
        (((uint32_t)(wm * 32 + (lane & 15))) * 36u + ((uint32_t)(lane >> 4)) * 4u) * 4u;
    const uint32_t b_row = (uint32_t)(wn * 64 + (lane & 7) + ((lane & 16) >> 1));
    const uint32_t b_ld0 = sbase + 2u * TILE_BYTES +
        (b_row * 36u + (((uint32_t)lane >> 3) & 1u) * 4u) * 4u;

    float c[2][8][4];
#pragma unroll
    for (int mt = 0; mt < 2; mt++)
#pragma unroll
        for (int nt = 0; nt < 8; nt++)
#pragma unroll
            for (int q = 0; q < 4; q++) c[mt][nt][q] = 0.f;

    const int nch = p.K / 32;

    // prologue: chunk 0 -> buf 0
#pragma unroll
    for (int i = 0; i < 4; i++) {
        cp16(a_stw + 16u * i, Ag + 4 * i);
        cp16(b_stw + 16u * i, Bg + 4 * i);
    }
    CP_COMMIT();

    for (int ck = 0; ck < nch; ++ck) {
        const int buf = ck & 1;
        const bool more = (ck + 1 < nch);
        if (more) {
            const uint32_t off = (uint32_t)(buf ^ 1) * TILE_BYTES;
            const float* ag = Ag + (ck + 1) * 32;
            const float* bg = Bg + (ck + 1) * 32;
#pragma unroll
            for (int i = 0; i < 4; i++) {
                cp16(a_stw + off + 16u * i, ag + 4 * i);
                cp16(b_stw + off + 16u * i, bg + 4 * i);
            }
            CP_COMMIT();
        }
        if (more) CP_WAIT(1); else CP_WAIT(0);
        __syncthreads();

        const uint32_t a_base = a_ld0 + (uint32_t)buf * TILE_BYTES;
        const uint32_t b_base = b_ld0 + (uint32_t)buf * TILE_BYTES;

        // fragment double-buffer: load k8, while MMA(k8) runs, LDSMs for k8+1
        uint32_t a[2][2][4], b[2][4][4];

#pragma unroll
        for (int mt = 0; mt < 2; mt++)
            LDMX4(a[0][mt][0], a[0][mt][1], a[0][mt][2], a[0][mt][3],
                  a_base + (uint32_t)mt * (16u * 36u * 4u));
#pragma unroll
        for (int pr = 0; pr < 4; pr++)
            LDMX4(b[0][pr][0], b[0][pr][1], b[0][pr][2], b[0][pr][3],
                  b_base + (uint32_t)pr * (16u * 36u * 4u));

#pragma unroll
        for (int k8 = 0; k8 < 4; k8++) {
            const int cur = k8 & 1;
            const int nxt = cur ^ 1;
            if (k8 < 3) {
#pragma unroll
                for (int mt = 0; mt < 2; mt++)
                    LDMX4(a[nxt][mt][0], a[nxt][mt][1], a[nxt][mt][2], a[nxt][mt][3],
                          a_base + (uint32_t)mt * (16u * 36u * 4u) + (uint32_t)(k8 + 1) * 32u);
#pragma unroll
                for (int pr = 0; pr < 4; pr++)
                    LDMX4(b[nxt][pr][0], b[nxt][pr][1], b[nxt][pr][2], b[nxt][pr][3],
                          b_base + (uint32_t)pr * (16u * 36u * 4u) + (uint32_t)(k8 + 1) * 32u);
            }
#pragma unroll
            for (int mt = 0; mt < 2; mt++)
#pragma unroll
                for (int q = 0; q < 4; q++) CVT_INPLACE(a[cur][mt][q]);
#pragma unroll
            for (int pr = 0; pr < 4; pr++)
#pragma unroll
                for (int q = 0; q < 4; q++) CVT_INPLACE(b[cur][pr][q]);
#pragma unroll
            for (int mt = 0; mt < 2; mt++)
#pragma unroll
                for (int nt = 0; nt < 8; nt++) {
                    const int pr = nt >> 1;
                    if (nt & 1) MMA_TF32(c[mt][nt],
                                         a[cur][mt][0], a[cur][mt][1], a[cur][mt][2], a[cur][mt][3],
                                         b[cur][pr][2], b[cur][pr][3]);
                    else        MMA_TF32(c[mt][nt],
                                         a[cur][mt][0], a[cur][mt][1], a[cur][mt][2], a[cur][mt][3],
                                         b[cur][pr][0], b[cur][pr][1]);
                }
        }
        __syncthreads();
    }

    const int rbase = row0 + wm * 32 + (lane >> 2);
    const int cbase = col0 + wn * 64 + (lane & 3) * 2;
#pragma unroll
    for (int mt = 0; mt < 2; mt++) {
#pragma unroll
        for (int nt = 0; nt < 8; nt++) {
            const int col = cbase + nt * 8;
            float bx = 0.f, by = 0.f;
            if (p.bias) { bx = p.bias[col]; by = p.bias[col + 1]; }
#pragma unroll
            for (int h = 0; h < 2; h++) {
                const int r = rbase + mt * 16 + h * 8;
                float vx = c[mt][nt][h * 2 + 0] * alpha + bx;
                float vy = c[mt][nt][h * 2 + 1] * alpha + by;
                if (p.relu) { vx = fmaxf(vx, 0.f); vy = fmaxf(vy, 0.f); }
                *reinterpret_cast<float2*>(C + (size_t)r * p.ldc + col) = make_float2(vx, vy);
            }
        }
    }
}

// =============================================================================
// band_att_mma (merged branches, R10 structure): 64 q x 128 k logits via
// tf32 mma, band softmax -> attb.
// =============================================================================
struct BA2 {
    const float* Q[2]; const float* Km[2]; float* attb[2]; int d[2]; int n;
};

#define BA_ATILE (64 * 36 * 4)    // 9216
#define BA_BTILE (128 * 36 * 4)   // 18432
#define BA_SMEM  (2 * BA_ATILE + 2 * BA_BTILE)  // 55296

__global__ void __launch_bounds__(256)
band_att_mma(BA2 pp)
{
    extern __shared__ char dsm[];
    const int br = blockIdx.y;
    const float* Q   = pp.Q[br];
    const float* Km  = pp.Km[br];
    float* attb      = pp.attb[br];
    const int d      = pp.d[br];
    const int n      = pp.n;

    const int tid  = threadIdx.x;
    const int lane = tid & 31;
    const int wid  = tid >> 5;
    const int wm   = wid & 1;
    const int wn   = wid >> 1;

    const int q0 = blockIdx.x * 64;
    const int jbase = q0 - 32;

    const uint32_t sbase = smem_u32(dsm);
    float* S = reinterpret_cast<float*>(dsm);

    const int larA = tid >> 2;
    const int lacA = (tid & 3) * 8;
    const int larB = tid >> 1;
    const int lacB = (tid & 1) * 16;
    const int jB   = min(max(jbase + larB, 0), n - 1);
    const float* Qg = Q  + (size_t)(q0 + larA) * d + lacA;
    const float* Kg = Km + (size_t)jB * d + lacB;
    const uint32_t a_stw = sbase + ((uint32_t)larA * 36u + (uint32_t)lacA) * 4u;
    const uint32_t b_stw = sbase + 2u * BA_ATILE +
                           ((uint32_t)larB * 36u + (uint32_t)lacB) * 4u;

    const uint32_t a_ld0 = sbase +
        (((uint32_t)(wm * 32 + (lane & 15))) * 36u + ((uint32_t)(lane >> 4)) * 4u) * 4u;
    const uint32_t b_row = (uint32_t)(wn * 32 + (lane & 7) + ((lane & 16) >> 1));
    const uint32_t b_ld0 = sbase + 2u * BA_ATILE +
        (b_row * 36u + (((uint32_t)lane >> 3) & 1u) * 4u) * 4u;

    float c[2][4][4];
#pragma unroll
    for (int mt = 0; mt < 2; mt++)
#pragma unroll
        for (int nt = 0; nt < 4; nt++)
#pragma unroll
            for (int q = 0; q < 4; q++) c[mt][nt][q] = 0.f;

    const int nch = d / 32;

#pragma unroll
    for (int i = 0; i < 2; i++) cp16(a_stw + 16u * i, Qg + 4 * i);
#pragma unroll
    for (int i = 0; i < 4; i++) cp16(b_stw + 16u * i, Kg + 4 * i);
    CP_COMMIT();

    for (int ck = 0; ck < nch; ++ck) {
        const int buf = ck & 1;
        const bool more = (ck + 1 < nch);
        if (more) {
            const float* qg = Qg + (ck + 1) * 32;
            const float* kg = Kg + (ck + 1) * 32;
            const uint32_t ao = (uint32_t)(buf ^ 1) * BA_ATILE;
            const uint32_t bo = (uint32_t)(buf ^ 1) * BA_BTILE;
#pragma unroll
            for (int i = 0; i < 2; i++) cp16(a_stw + ao + 16u * i, qg + 4 * i);
#pragma unroll
            for (int i = 0; i < 4; i++) cp16(b_stw + bo + 16u * i, kg + 4 * i);
            CP_COMMIT();
        }
        if (more) CP_WAIT(1); else CP_WAIT(0);
        __syncthreads();

        const uint32_t a_base = a_ld0 + (uint32_t)buf * BA_ATILE;
        const uint32_t b_base = b_ld0 + (uint32_t)buf * BA_BTILE;
#pragma unroll
        for (int k8 = 0; k8 < 4; k8++) {
            uint32_t a[2][4], b[2][4];
#pragma unroll
            for (int mt = 0; mt < 2; mt++) {
                LDMX4(a[mt][0], a[mt][1], a[mt][2], a[mt][3],
                      a_base + (uint32_t)mt * (16u * 36u * 4u) + (uint32_t)k8 * 32u);
#pragma unroll
                for (int q = 0; q < 4; q++) CVT_INPLACE(a[mt][q]);
            }
#pragma unroll
            for (int pr = 0; pr < 2; pr++) {
                LDMX4(b[pr][0], b[pr][1], b[pr][2], b[pr][3],
                      b_base + (uint32_t)pr * (16u * 36u * 4u) + (uint32_t)k8 * 32u);
#pragma unroll
                for (int q = 0; q < 4; q++) CVT_INPLACE(b[pr][q]);
            }
#pragma unroll
            for (int mt = 0; mt < 2; mt++)
#pragma unroll
                for (int nt = 0; nt < 4; nt++) {
                    const int pr = nt >> 1;
                    if (nt & 1) MMA_TF32(c[mt][nt], a[mt][0], a[mt][1], a[mt][2], a[mt][3],
                                         b[pr][2], b[pr][3]);
                    else        MMA_TF32(c[mt][nt], a[mt][0], a[mt][1], a[mt][2], a[mt][3],
                                         b[pr][0], b[pr][1]);
                }
        }
        __syncthreads();
    }

    // store logits into S[64][132]
#pragma unroll
    for (int mt = 0; mt < 2; mt++)
#pragma unroll
        for (int nt = 0; nt < 4; nt++)
#pragma unroll
            for (int h = 0; h < 2; h++) {
                const int r = wm * 32 + mt * 16 + (lane >> 2) + h * 8;
                const int cc = wn * 32 + nt * 8 + (lane & 3) * 2;
                S[r * 132 + cc]     = c[mt][nt][h * 2 + 0];
                S[r * 132 + cc + 1] = c[mt][nt][h * 2 + 1];
            }
    __syncthreads();

    // band softmax
    const int i = wid * 8 + (lane >> 2);
    const int sl = lane & 3;
    float vals[10];
    float m = -1e30f;
#pragma unroll
    for (int k = 0; k < 10; k++) {
        const int s = sl + 4 * k;
        float v = -1e30f;
        if (s < BANDW) {
            const int j = q0 + i + s - (APP - 1);
            if (j >= 0 && j < n) v = S[i * 132 + (i + 13 + s)];
        }
        vals[k] = v;
        m = fmaxf(m, v);
    }
    m = fmaxf(m, __shfl_xor_sync(0xffffffffu, m, 1));
    m = fmaxf(m, __shfl_xor_sync(0xffffffffu, m, 2));
    float sum = 0.f;
#pragma unroll
    for (int k = 0; k < 10; k++) {
        const float e = expf(vals[k] - m);
        vals[k] = e;
        sum += e;
    }
    sum += __shfl_xor_sync(0xffffffffu, sum, 1);
    sum += __shfl_xor_sync(0xffffffffu, sum, 2);
    const float inv = 1.f / sum;
#pragma unroll
    for (int k = 0; k < 10; k++) {
        const int s = sl + 4 * k;
        if (s < BANDW)
            attb[(size_t)(q0 + i) * BANDP + s] = vals[k] * inv;
    }
}

// =============================================================================
// band_apply (chunk-parallel): grid (nb, nchunk). 64 outputs x 128 cols per CTA.
// =============================================================================
#define BP_SMEM 62464

__global__ void __launch_bounds__(256)
band_apply_c(const float* __restrict__ attb, const float* __restrict__ V,
             float* __restrict__ Y, int n, int d)
{
    extern __shared__ char dsm[];
    float* ws = reinterpret_cast<float*>(dsm);            // [64][40]
    float* Vs = reinterpret_cast<float*>(dsm + 10240);    // [102][128]

    const int tid = threadIdx.x;
    const int q0 = blockIdx.x * 64;
    const int ch = blockIdx.y;
    const int jbase = q0 - (APP - 1);

    for (int idx = tid; idx < 64 * BANDW; idx += 256) {
        const int i = idx / BANDW;
        const int s = idx - i * BANDW;
        const int j = q0 + i + s - (APP - 1);
        float w = 0.f;
        if (j >= 0 && j < n) w = attb[(size_t)j * BANDP + (38 - s)];
        ws[i * 40 + s] = w;
    }

    for (int idx = tid; idx < 102 * 32; idx += 256) {
        const int row = idx >> 5;
        const int c4  = idx & 31;
        const int j = min(max(jbase + row, 0), n - 1);
        *reinterpret_cast<float4*>(&Vs[row * 128 + c4 * 4]) =
            *reinterpret_cast<const float4*>(V + (size_t)j * d + ch * 128 + c4 * 4);
    }
    __syncthreads();

    const int qg = tid >> 5;
    const int cg = tid & 31;

    float4 acc[8];
#pragma unroll
    for (int q = 0; q < 8; q++) acc[q] = make_float4(0.f, 0.f, 0.f, 0.f);

#pragma unroll
    for (int r = 0; r <= 45; r++) {
        const float4 v4 = *reinterpret_cast<const float4*>(&Vs[(qg * 8 + r) * 128 + cg * 4]);
#pragma unroll
        for (int q = 0; q < 8; q++) {
            const int s = r - q;
            if (s >= 0 && s < BANDW) {
                const float w = ws[(qg * 8 + q) * 40 + s];
                acc[q].x = fmaf(w, v4.x, acc[q].x);
                acc[q].y = fmaf(w, v4.y, acc[q].y);
                acc[q].z = fmaf(w, v4.z, acc[q].z);
                acc[q].w = fmaf(w, v4.w, acc[q].w);
            }
        }
    }
#pragma unroll
    for (int q = 0; q < 8; q++) {
        const int i = q0 + qg * 8 + q;
        *reinterpret_cast<float4*>(Y + (size_t)i * d + ch * 128 + cg * 4) = acc[q];
    }
}

// ---------------- residual + layernorm (merged branches) ---------------------
struct LN2 {
    const float* y[2]; const float* x[2];
    const float* g[2]; const float* b[2];
    float* dst[2]; int d[2]; int stride[2];
};

__global__ void ln_res2(LN2 pp)
{
    __shared__ float sh1[8], sh2[8];
    __shared__ float s_mu, s_rstd;
    const int br = blockIdx.y;
    const float* y = pp.y[br];
    const float* x = pp.x[br];
    const float* g = pp.g[br];
    const float* b = pp.b[br];
    float* dst = pp.dst[br];
    const int d = pp.d[br];
    const int dstride = pp.stride[br];

    const int i = blockIdx.x;
    const int lane = threadIdx.x & 31, wid = threadIdx.x >> 5;

    float sum = 0.f, sq = 0.f;
    for (int c = threadIdx.x; c < d; c += blockDim.x) {
        float v = y[(size_t)i * d + c] + x[(size_t)i * d + c];
        sum += v; sq = fmaf(v, v, sq);
    }
#pragma unroll
    for (int o = 16; o; o >>= 1) {
        sum += __shfl_down_sync(0xffffffffu, sum, o);
        sq  += __shfl_down_sync(0xffffffffu, sq,  o);
    }
    if (lane == 0) { sh1[wid] = sum; sh2[wid] = sq; }
    __syncthreads();
    if (wid == 0) {
        float s = (lane < 8) ? sh1[lane] : 0.f;
        float q = (lane < 8) ? sh2[lane] : 0.f;
#pragma unroll
        for (int o = 4; o; o >>= 1) {
            s += __shfl_down_sync(0xffffffffu, s, o);
            q += __shfl_down_sync(0xffffffffu, q, o);
        }
        if (lane == 0) {
            const float mu = s / d;
            float var = q / d - mu * mu;
            s_mu = mu;
            s_rstd = rsqrtf(var + 1e-6f);
        }
    }
    __syncthreads();
    const float mu = s_mu, rstd = s_rstd;
    for (int c = threadIdx.x; c < d; c += blockDim.x) {
        float v = y[(size_t)i * d + c] + x[(size_t)i * d + c];
        dst[(size_t)i * dstride + c] = (v - mu) * rstd * g[c] + b[c];
    }
}

// ---------------- fused LN(h) + sigmoid head ---------------------------------
__global__ void head_fused(const float* __restrict__ h, const float* __restrict__ g,
                           const float* __restrict__ b, const float* __restrict__ w,
                           const float* __restrict__ kd_b, float* __restrict__ out, int d)
{
    __shared__ float sh[8][5];
    const int i = blockIdx.x;
    const int lane = threadIdx.x & 31, wid = threadIdx.x >> 5;

    float sum = 0.f, sq = 0.f, hgw = 0.f, gw = 0.f, bw = 0.f;
    for (int c = threadIdx.x; c < d; c += blockDim.x) {
        const float hv = h[(size_t)i * d + c];
        const float gc = g[c], bc = b[c], wc = w[c];
        sum += hv; sq = fmaf(hv, hv, sq);
        const float gwc = gc * wc;
        hgw = fmaf(hv, gwc, hgw);
        gw += gwc;
        bw = fmaf(bc, wc, bw);
    }
#pragma unroll
    for (int o = 16; o; o >>= 1) {
        sum += __shfl_down_sync(0xffffffffu, sum, o);
        sq  += __shfl_down_sync(0xffffffffu, sq,  o);
        hgw += __shfl_down_sync(0xffffffffu, hgw, o);
        gw  += __shfl_down_sync(0xffffffffu, gw,  o);
        bw  += __shfl_down_sync(0xffffffffu, bw,  o);
    }
    if (lane == 0) {
        sh[wid][0] = sum; sh[wid][1] = sq; sh[wid][2] = hgw;
        sh[wid][3] = gw;  sh[wid][4] = bw;
    }
    __syncthreads();
    if (wid == 0 && lane == 0) {
        float s = 0.f, q = 0.f, hg = 0.f, gg = 0.f, bb = 0.f;
#pragma unroll
        for (int k = 0; k < 8; k++) {
            s += sh[k][0]; q += sh[k][1]; hg += sh[k][2];
            gg += sh[k][3]; bb += sh[k][4];
        }
        const float mu = s / d;
        const float var = q / d - mu * mu;
        const float rstd = rsqrtf(var + 1e-6f);
        const float sc = rstd * (hg - mu * gg) + bb + kd_b[0];
        out[i] = 1.f / (1.f + expf(-sc));
    }
}

// ---------------- scatter band attention into dense [N, 2N] output ----------
__global__ void scatter_att(const float* __restrict__ attv, const float* __restrict__ atta,
                            float* __restrict__ out, int n)
{
    const int i = blockIdx.x;
    const size_t base = (size_t)n + (size_t)i * 2u * (size_t)n;
    const int j0 = max(i - (APP - 1), 0);
    const int j1 = min(i + (APP - 1), n - 1);
    for (int k = threadIdx.x; k <= j1 - j0; k += blockDim.x) {
        const int j = j0 + k;
        const float av = attv[(size_t)i * BANDP + (j - i + (APP - 1))];
        const float aa = atta[(size_t)i * BANDP + (j - i + (APP - 1))];
        out[base + j]     = av;
        out[base + n + j] = aa;
    }
}

// ---------------- launch ------------------------------------------------------
extern "C" void kernel_launch(void* const* d_in, const int* in_sizes, int n_in,
                              void* d_out, int out_size)
{
    const float* x     = (const float*)d_in[0];
    const float* xa    = (const float*)d_in[1];
    const float* Wk_v  = (const float*)d_in[4];
    const float* Wq_v  = (const float*)d_in[5];
    const float* Wv_v  = (const float*)d_in[6];
    const float* Wo_v  = (const float*)d_in[7];
    const float* Wk_a  = (const float*)d_in[8];
    const float* Wq_a  = (const float*)d_in[9];
    const float* Wv_a  = (const float*)d_in[10];
    const float* Wo_a  = (const float*)d_in[11];
    const float* ka_w  = (const float*)d_in[12];
    const float* ka_b  = (const float*)d_in[13];
    const float* kd_w  = (const float*)d_in[14];
    const float* kd_b  = (const float*)d_in[15];
    const float* ln_y_g  = (const float*)d_in[16];
    const float* ln_y_b  = (const float*)d_in[17];
    const float* ln_ya_g = (const float*)d_in[18];
    const float* ln_ya_b = (const float*)d_in[19];
    const float* ln_ka_g = (const float*)d_in[20];
    const float* ln_ka_b = (const float*)d_in[21];

    const int n = in_sizes[0] / DV;   // 6144

    cudaFuncSetAttribute(tgemm, cudaFuncAttributeMaxDynamicSharedMemorySize, TG_SMEM);
    cudaFuncSetAttribute(band_att_mma, cudaFuncAttributeMaxDynamicSharedMemorySize, BA_SMEM);
    cudaFuncSetAttribute(band_apply_c, cudaFuncAttributeMaxDynamicSharedMemorySize, BP_SMEM);

    float *Kv, *Qv, *Vv, *Yv, *Yov, *Ka, *Qa, *Va, *Ya, *Yoa, *attv, *atta, *ycomb, *h;
    cudaGetSymbolAddress((void**)&Kv,  g_Kv);
    cudaGetSymbolAddress((void**)&Qv,  g_Qv);
    cudaGetSymbolAddress((void**)&Vv,  g_Vv);
    cudaGetSymbolAddress((void**)&Yv,  g_Yv);
    cudaGetSymbolAddress((void**)&Yov, g_Yov);
    cudaGetSymbolAddress((void**)&Ka,  g_Ka);
    cudaGetSymbolAddress((void**)&Qa,  g_Qa);
    cudaGetSymbolAddress((void**)&Va,  g_Va);
    cudaGetSymbolAddress((void**)&Ya,  g_Ya);
    cudaGetSymbolAddress((void**)&Yoa, g_Yoa);
    cudaGetSymbolAddress((void**)&attv, g_attv);
    cudaGetSymbolAddress((void**)&atta, g_atta);
    cudaGetSymbolAddress((void**)&ycomb, g_ycomb);
    cudaGetSymbolAddress((void**)&h,   g_h);

    float* out = (float*)d_out;
    const size_t full_elems = (size_t)n + 2ull * (size_t)n * (size_t)n;
    const size_t clear = ((size_t)out_size >= full_elems) ? full_elems : (size_t)out_size;
    cudaMemsetAsync(out, 0, clear * sizeof(float), 0);

    const int nb = n / 64;   // 96 band blocks

    // --- video QKV (batched z) ---
    {
        TG p; p.A = x;
        p.B0 = Wk_v; p.B1 = Wq_v; p.B2 = Wv_v;
        p.C0 = Kv;   p.C1 = Qv;   p.C2 = Vv;
        p.a0 = 1.f;  p.a1 = 0.06f; p.a2 = 1.f;
        p.bias = nullptr; p.relu = 0;
        p.K = DV; p.lda = DV; p.ldb = DV; p.ldc = DV;
        tgemm<<<dim3(DV / 128, n / 128, 3), 256, TG_SMEM>>>(p);
    }
    // --- audio QKV (batched z) ---
    {
        TG p; p.A = xa;
        p.B0 = Wk_a; p.B1 = Wq_a; p.B2 = Wv_a;
        p.C0 = Ka;   p.C1 = Qa;   p.C2 = Va;
        p.a0 = 1.f;  p.a1 = 0.06f; p.a2 = 1.f;
        p.bias = nullptr; p.relu = 0;
        p.K = DA; p.lda = DA; p.ldb = DA; p.ldc = DA;
        tgemm<<<dim3(DA / 128, n / 128, 3), 256, TG_SMEM>>>(p);
    }

    // --- merged band attention (video + audio) ---
    {
        BA2 p;
        p.Q[0] = Qv; p.Km[0] = Kv; p.attb[0] = attv; p.d[0] = DV;
        p.Q[1] = Qa; p.Km[1] = Ka; p.attb[1] = atta; p.d[1] = DA;
        p.n = n;
        band_att_mma<<<dim3(nb, 2), 256, BA_SMEM>>>(p);
    }

    // --- chunk-parallel band apply ---
    band_apply_c<<<dim3(nb, DV / 128), 256, BP_SMEM>>>(attv, Vv, Yv, n, DV);
    band_apply_c<<<dim3(nb, DA / 128), 256, BP_SMEM>>>(atta, Va, Ya, n, DA);

    // --- video Wo ---
    {
        TG p; p.A = Yv;
        p.B0 = Wo_v; p.B1 = Wo_v; p.B2 = Wo_v;
        p.C0 = Yov;  p.C1 = Yov;  p.C2 = Yov;
        p.a0 = 1.f; p.a1 = 1.f; p.a2 = 1.f;
        p.bias = nullptr; p.relu = 0;
        p.K = DV; p.lda = DV; p.ldb = DV; p.ldc = DV;
        tgemm<<<dim3(DV / 128, n / 128, 1), 256, TG_SMEM>>>(p);
    }
    // --- audio Wo ---
    {
        TG p; p.A = Ya;
        p.B0 = Wo_a; p.B1 = Wo_a; p.B2 = Wo_a;
        p.C0 = Yoa;  p.C1 = Yoa;  p.C2 = Yoa;
        p.a0 = 1.f; p.a1 = 1.f; p.a2 = 1.f;
        p.bias = nullptr; p.relu = 0;
        p.K = DA; p.lda = DA; p.ldb = DA; p.ldc = DA;
        tgemm<<<dim3(DA / 128, n / 128, 1), 256, TG_SMEM>>>(p);
    }

    // --- merged residual LN (video + audio) -> ycomb ---
    {
        LN2 p;
        p.y[0] = Yov; p.x[0] = x;  p.g[0] = ln_y_g;  p.b[0] = ln_y_b;
        p.dst[0] = ycomb;      p.d[0] = DV; p.stride[0] = DC;
        p.y[1] = Yoa; p.x[1] = xa; p.g[1] = ln_ya_g; p.b[1] = ln_ya_b;
        p.dst[1] = ycomb + DV; p.d[1] = DA; p.stride[1] = DC;
        ln_res2<<<dim3(n, 2), 256>>>(p);
    }

    // --- MLP head GEMM ---
    {
        TG p; p.A = ycomb;
        p.B0 = ka_w; p.B1 = ka_w; p.B2 = ka_w;
        p.C0 = h;    p.C1 = h;    p.C2 = h;
        p.a0 = 1.f; p.a1 = 1.f; p.a2 = 1.f;
        p.bias = ka_b; p.relu = 1;
        p.K = DC; p.lda = DC; p.ldb = DC; p.ldc = DH;
        tgemm<<<dim3(DH / 128, n / 128, 1), 256, TG_SMEM>>>(p);
    }

    // --- fused LN + sigmoid head ---
    head_fused<<<n, 256>>>(h, ln_ka_g, ln_ka_b, kd_w, kd_b, out, DH);

    // --- dense attention output ---
    if ((size_t)out_size >= full_elems)
        scatter_att<<<n, 64>>>(attv, atta, out, n);
}

// round 17
// speedup vs baseline: 1.4055x; 1.0348x over previous
#include <cuda_runtime.h>
#include <cstdint>
#include <math.h>

#define NTOK 6144
#define DV   1024
#define DA   128
#define DC   (DV + DA)   // 1152
#define DH   1024
#define APP  20
#define BANDW 39
#define BANDP 40

// ---------------- scratch (static device globals; no allocation) -------------
// g_Kv repurposed: [0,1M) WqT, [1M,2M) WkT, [2M,3M) Mt  (video K no longer stored)
__device__ float g_Kv [NTOK * DV];
__device__ float g_Qv [NTOK * DV];   // holds P (video)
__device__ float g_Vv [NTOK * DV];
__device__ float g_Yv [NTOK * DV];
__device__ float g_Yov[NTOK * DV];
__device__ float g_Ka [NTOK * DA];
__device__ float g_Qa [NTOK * DA];
__device__ float g_Va [NTOK * DA];
__device__ float g_Ya [NTOK * DA];
__device__ float g_Yoa[NTOK * DA];
__device__ float g_attv[NTOK * BANDP];
__device__ float g_atta[NTOK * BANDP];
__device__ float g_ycomb[NTOK * DC];
__device__ float g_h  [NTOK * DH];

// ======================= helpers =============================================
__device__ __forceinline__ uint32_t smem_u32(const void* p) {
    uint32_t r;
    asm("{ .reg .u64 t; cvta.to.shared.u64 t, %1; cvt.u32.u64 %0, t; }"
        : "=r"(r) : "l"(p));
    return r;
}

__device__ __forceinline__ uint32_t f2tf32(float x) {
    uint32_t r;
    asm("cvt.rna.tf32.f32 %0, %1;" : "=r"(r) : "f"(x));
    return r;
}

__device__ __forceinline__ void cp16(uint32_t dst, const void* src) {
    asm volatile("cp.async.ca.shared.global [%0], [%1], 16;" :: "r"(dst), "l"(src));
}
#define CP_COMMIT() asm volatile("cp.async.commit_group;" ::: "memory")
#define CP_WAIT(n)  asm volatile("cp.async.wait_group %0;" :: "n"(n) : "memory")

#define LDMX4(r0, r1, r2, r3, addr) \
    asm volatile("ldmatrix.sync.aligned.m8n8.x4.shared.b16 {%0,%1,%2,%3}, [%4];" \
                 : "=r"(r0), "=r"(r1), "=r"(r2), "=r"(r3) : "r"(addr))

#define MMA_TF32(c, a0, a1, a2, a3, b0, b1) \
    asm volatile("mma.sync.aligned.m16n8k8.row.col.f32.tf32.tf32.f32 " \
                 "{%0,%1,%2,%3}, {%4,%5,%6,%7}, {%8,%9}, {%0,%1,%2,%3};" \
                 : "+f"((c)[0]), "+f"((c)[1]), "+f"((c)[2]), "+f"((c)[3]) \
                 : "r"(a0), "r"(a1), "r"(a2), "r"(a3), "r"(b0), "r"(b1))

#define CVT_INPLACE(r) (r) = f2tf32(__uint_as_float(r))

// ---------------- 32x32 tiled transpose, two matrices via grid.z -------------
__global__ void transpose2(const float* __restrict__ s0, float* __restrict__ d0,
                           const float* __restrict__ s1, float* __restrict__ d1, int nn)
{
    __shared__ float t[32][33];
    const float* s = blockIdx.z ? s1 : s0;
    float* d       = blockIdx.z ? d1 : d0;
    const int x0 = blockIdx.x * 32, y0 = blockIdx.y * 32;
    for (int r = threadIdx.y; r < 32; r += 8)
        t[r][threadIdx.x] = s[(size_t)(y0 + r) * nn + x0 + threadIdx.x];
    __syncthreads();
    for (int r = threadIdx.y; r < 32; r += 8)
        d[(size_t)(x0 + r) * nn + y0 + threadIdx.x] = t[threadIdx.x][r];
}

// =============================================================================
// tgemm (R10 proven config): C[z] = alpha[z] * A * B[z]^T (+bias)(relu)
// tf32 mma + 2-stage cp.async. CTA tile 128x128, BK=32, 8 warps (4M x 2N).
// =============================================================================
struct TG {
    const float* A0; const float* A1; const float* A2;   // per-z A (usually same)
    const float *B0, *B1, *B2;
    float *C0, *C1, *C2;
    float a0, a1, a2;
    const float* bias;
    int relu;
    int K, lda, ldb, ldc;
};

#define TILE_BYTES (128 * 36 * 4)           // 18432
#define TG_SMEM    (4 * TILE_BYTES)         // 73728

__global__ void __launch_bounds__(256)
tgemm(TG p)
{
    extern __shared__ char dsm[];
    const int tid  = threadIdx.x;
    const int lane = tid & 31;
    const int wid  = tid >> 5;
    const int wm   = wid & 3;
    const int wn   = wid >> 2;

    const int row0 = blockIdx.y * 128;
    const int col0 = blockIdx.x * 128;
    const int z = blockIdx.z;
    const float* A = (z == 0) ? p.A0 : (z == 1) ? p.A1 : p.A2;
    const float* B = (z == 0) ? p.B0 : (z == 1) ? p.B1 : p.B2;
    float*       C = (z == 0) ? p.C0 : (z == 1) ? p.C1 : p.C2;
    const float alpha = (z == 0) ? p.a0 : (z == 1) ? p.a1 : p.a2;

    const uint32_t sbase = smem_u32(dsm);

    const int lrow = tid >> 1;
    const int lcol = (tid & 1) * 16;
    const float* Ag = A + (size_t)(row0 + lrow) * p.lda + lcol;
    const float* Bg = B + (size_t)(col0 + lrow) * p.ldb + lcol;
    const uint32_t a_stw = sbase + ((uint32_t)lrow * 36u + (uint32_t)lcol) * 4u;
    const uint32_t b_stw = a_stw + 2u * TILE_BYTES;

    const uint32_t a_ld0 = sbase +
        (((uint32_t)(wm * 32 + (lane & 15))) * 36u + ((uint32_t)(lane >> 4)) * 4u) * 4u;
    const uint32_t b_row = (uint32_t)(wn * 64 + (lane & 7) + ((lane & 16) >> 1));
    const uint32_t b_ld0 = sbase + 2u * TILE_BYTES +
        (b_row * 36u + (((uint32_t)lane >> 3) & 1u) * 4u) * 4u;

    float c[2][8][4];
#pragma unroll
    for (int mt = 0; mt < 2; mt++)
#pragma unroll
        for (int nt = 0; nt < 8; nt++)
#pragma unroll
            for (int q = 0; q < 4; q++) c[mt][nt][q] = 0.f;

    const int nch = p.K / 32;

#pragma unroll
    for (int i = 0; i < 4; i++) {
        cp16(a_stw + 16u * i, Ag + 4 * i);
        cp16(b_stw + 16u * i, Bg + 4 * i);
    }
    CP_COMMIT();

    for (int ck = 0; ck < nch; ++ck) {
        const int buf = ck & 1;
        const bool more = (ck + 1 < nch);
        if (more) {
            const uint32_t off = (uint32_t)(buf ^ 1) * TILE_BYTES;
            const float* ag = Ag + (ck + 1) * 32;
            const float* bg = Bg + (ck + 1) * 32;
#pragma unroll
            for (int i = 0; i < 4; i++) {
                cp16(a_stw + off + 16u * i, ag + 4 * i);
                cp16(b_stw + off + 16u * i, bg + 4 * i);
            }
            CP_COMMIT();
        }
        if (more) CP_WAIT(1); else CP_WAIT(0);
        __syncthreads();

        const uint32_t a_base = a_ld0 + (uint32_t)buf * TILE_BYTES;
        const uint32_t b_base = b_ld0 + (uint32_t)buf * TILE_BYTES;
#pragma unroll
        for (int k8 = 0; k8 < 4; k8++) {
            uint32_t a[2][4], b[4][4];
#pragma unroll
            for (int mt = 0; mt < 2; mt++) {
                LDMX4(a[mt][0], a[mt][1], a[mt][2], a[mt][3],
                      a_base + (uint32_t)mt * (16u * 36u * 4u) + (uint32_t)k8 * 32u);
#pragma unroll
                for (int q = 0; q < 4; q++) CVT_INPLACE(a[mt][q]);
            }
#pragma unroll
            for (int pr = 0; pr < 4; pr++) {
                LDMX4(b[pr][0], b[pr][1], b[pr][2], b[pr][3],
                      b_base + (uint32_t)pr * (16u * 36u * 4u) + (uint32_t)k8 * 32u);
#pragma unroll
                for (int q = 0; q < 4; q++) CVT_INPLACE(b[pr][q]);
            }
#pragma unroll
            for (int mt = 0; mt < 2; mt++)
#pragma unroll
                for (int nt = 0; nt < 8; nt++) {
                    const int pr = nt >> 1;
                    if (nt & 1) MMA_TF32(c[mt][nt], a[mt][0], a[mt][1], a[mt][2], a[mt][3],
                                         b[pr][2], b[pr][3]);
                    else        MMA_TF32(c[mt][nt], a[mt][0], a[mt][1], a[mt][2], a[mt][3],
                                         b[pr][0], b[pr][1]);
                }
        }
        __syncthreads();
    }

    const int rbase = row0 + wm * 32 + (lane >> 2);
    const int cbase = col0 + wn * 64 + (lane & 3) * 2;
#pragma unroll
    for (int mt = 0; mt < 2; mt++) {
#pragma unroll
        for (int nt = 0; nt < 8; nt++) {
            const int col = cbase + nt * 8;
            float bx = 0.f, by = 0.f;
            if (p.bias) { bx = p.bias[col]; by = p.bias[col + 1]; }
#pragma unroll
            for (int h = 0; h < 2; h++) {
                const int r = rbase + mt * 16 + h * 8;
                float vx = c[mt][nt][h * 2 + 0] * alpha + bx;
                float vy = c[mt][nt][h * 2 + 1] * alpha + by;
                if (p.relu) { vx = fmaxf(vx, 0.f); vy = fmaxf(vy, 0.f); }
                *reinterpret_cast<float2*>(C + (size_t)r * p.ldc + col) = make_float2(vx, vy);
            }
        }
    }
}

// =============================================================================
// band_att_mma (merged branches, R10 structure): 64 q x 128 k logits via
// tf32 mma, band softmax -> attb.  Video: Q=P, Km=x.  Audio: Q=Qa, Km=Ka.
// =============================================================================
struct BA2 {
    const float* Q[2]; const float* Km[2]; float* attb[2]; int d[2]; int n;
};

#define BA_ATILE (64 * 36 * 4)    // 9216
#define BA_BTILE (128 * 36 * 4)   // 18432
#define BA_SMEM  (2 * BA_ATILE + 2 * BA_BTILE)  // 55296

__global__ void __launch_bounds__(256)
band_att_mma(BA2 pp)
{
    extern __shared__ char dsm[];
    const int br = blockIdx.y;
    const float* Q   = pp.Q[br];
    const float* Km  = pp.Km[br];
    float* attb      = pp.attb[br];
    const int d      = pp.d[br];
    const int n      = pp.n;

    const int tid  = threadIdx.x;
    const int lane = tid & 31;
    const int wid  = tid >> 5;
    const int wm   = wid & 1;
    const int wn   = wid >> 1;

    const int q0 = blockIdx.x * 64;
    const int jbase = q0 - 32;

    const uint32_t sbase = smem_u32(dsm);
    float* S = reinterpret_cast<float*>(dsm);

    const int larA = tid >> 2;
    const int lacA = (tid & 3) * 8;
    const int larB = tid >> 1;
    const int lacB = (tid & 1) * 16;
    const int jB   = min(max(jbase + larB, 0), n - 1);
    const float* Qg = Q  + (size_t)(q0 + larA) * d + lacA;
    const float* Kg = Km + (size_t)jB * d + lacB;
    const uint32_t a_stw = sbase + ((uint32_t)larA * 36u + (uint32_t)lacA) * 4u;
    const uint32_t b_stw = sbase + 2u * BA_ATILE +
                           ((uint32_t)larB * 36u + (uint32_t)lacB) * 4u;

    const uint32_t a_ld0 = sbase +
        (((uint32_t)(wm * 32 + (lane & 15))) * 36u + ((uint32_t)(lane >> 4)) * 4u) * 4u;
    const uint32_t b_row = (uint32_t)(wn * 32 + (lane & 7) + ((lane & 16) >> 1));
    const uint32_t b_ld0 = sbase + 2u * BA_ATILE +
        (b_row * 36u + (((uint32_t)lane >> 3) & 1u) * 4u) * 4u;

    float c[2][4][4];
#pragma unroll
    for (int mt = 0; mt < 2; mt++)
#pragma unroll
        for (int nt = 0; nt < 4; nt++)
#pragma unroll
            for (int q = 0; q < 4; q++) c[mt][nt][q] = 0.f;

    const int nch = d / 32;

#pragma unroll
    for (int i = 0; i < 2; i++) cp16(a_stw + 16u * i, Qg + 4 * i);
#pragma unroll
    for (int i = 0; i < 4; i++) cp16(b_stw + 16u * i, Kg + 4 * i);
    CP_COMMIT();

    for (int ck = 0; ck < nch; ++ck) {
        const int buf = ck & 1;
        const bool more = (ck + 1 < nch);
        if (more) {
            const float* qg = Qg + (ck + 1) * 32;
            const float* kg = Kg + (ck + 1) * 32;
            const uint32_t ao = (uint32_t)(buf ^ 1) * BA_ATILE;
            const uint32_t bo = (uint32_t)(buf ^ 1) * BA_BTILE;
#pragma unroll
            for (int i = 0; i < 2; i++) cp16(a_stw + ao + 16u * i, qg + 4 * i);
#pragma unroll
            for (int i = 0; i < 4; i++) cp16(b_stw + bo + 16u * i, kg + 4 * i);
            CP_COMMIT();
        }
        if (more) CP_WAIT(1); else CP_WAIT(0);
        __syncthreads();

        const uint32_t a_base = a_ld0 + (uint32_t)buf * BA_ATILE;
        const uint32_t b_base = b_ld0 + (uint32_t)buf * BA_BTILE;
#pragma unroll
        for (int k8 = 0; k8 < 4; k8++) {
            uint32_t a[2][4], b[2][4];
#pragma unroll
            for (int mt = 0; mt < 2; mt++) {
                LDMX4(a[mt][0], a[mt][1], a[mt][2], a[mt][3],
                      a_base + (uint32_t)mt * (16u * 36u * 4u) + (uint32_t)k8 * 32u);
#pragma unroll
                for (int q = 0; q < 4; q++) CVT_INPLACE(a[mt][q]);
            }
#pragma unroll
            for (int pr = 0; pr < 2; pr++) {
                LDMX4(b[pr][0], b[pr][1], b[pr][2], b[pr][3],
                      b_base + (uint32_t)pr * (16u * 36u * 4u) + (uint32_t)k8 * 32u);
#pragma unroll
                for (int q = 0; q < 4; q++) CVT_INPLACE(b[pr][q]);
            }
#pragma unroll
            for (int mt = 0; mt < 2; mt++)
#pragma unroll
                for (int nt = 0; nt < 4; nt++) {
                    const int pr = nt >> 1;
                    if (nt & 1) MMA_TF32(c[mt][nt], a[mt][0], a[mt][1], a[mt][2], a[mt][3],
                                         b[pr][2], b[pr][3]);
                    else        MMA_TF32(c[mt][nt], a[mt][0], a[mt][1], a[mt][2], a[mt][3],
                                         b[pr][0], b[pr][1]);
                }
        }
        __syncthreads();
    }

    // store logits into S[64][132]
#pragma unroll
    for (int mt = 0; mt < 2; mt++)
#pragma unroll
        for (int nt = 0; nt < 4; nt++)
#pragma unroll
            for (int h = 0; h < 2; h++) {
                const int r = wm * 32 + mt * 16 + (lane >> 2) + h * 8;
                const int cc = wn * 32 + nt * 8 + (lane & 3) * 2;
                S[r * 132 + cc]     = c[mt][nt][h * 2 + 0];
                S[r * 132 + cc + 1] = c[mt][nt][h * 2 + 1];
            }
    __syncthreads();

    // band softmax
    const int i = wid * 8 + (lane >> 2);
    const int sl = lane & 3;
    float vals[10];
    float m = -1e30f;
#pragma unroll
    for (int k = 0; k < 10; k++) {
        const int s = sl + 4 * k;
        float v = -1e30f;
        if (s < BANDW) {
            const int j = q0 + i + s - (APP - 1);
            if (j >= 0 && j < n) v = S[i * 132 + (i + 13 + s)];
        }
        vals[k] = v;
        m = fmaxf(m, v);
    }
    m = fmaxf(m, __shfl_xor_sync(0xffffffffu, m, 1));
    m = fmaxf(m, __shfl_xor_sync(0xffffffffu, m, 2));
    float sum = 0.f;
#pragma unroll
    for (int k = 0; k < 10; k++) {
        const float e = expf(vals[k] - m);
        vals[k] = e;
        sum += e;
    }
    sum += __shfl_xor_sync(0xffffffffu, sum, 1);
    sum += __shfl_xor_sync(0xffffffffu, sum, 2);
    const float inv = 1.f / sum;
#pragma unroll
    for (int k = 0; k < 10; k++) {
        const int s = sl + 4 * k;
        if (s < BANDW)
            attb[(size_t)(q0 + i) * BANDP + s] = vals[k] * inv;
    }
}

// =============================================================================
// band_apply (chunk-parallel): grid (nb, nchunk). 64 outputs x 128 cols per CTA.
// =============================================================================
#define BP_SMEM 62464

__global__ void __launch_bounds__(256)
band_apply_c(const float* __restrict__ attb, const float* __restrict__ V,
             float* __restrict__ Y, int n, int d)
{
    extern __shared__ char dsm[];
    float* ws = reinterpret_cast<float*>(dsm);            // [64][40]
    float* Vs = reinterpret_cast<float*>(dsm + 10240);    // [102][128]

    const int tid = threadIdx.x;
    const int q0 = blockIdx.x * 64;
    const int ch = blockIdx.y;
    const int jbase = q0 - (APP - 1);

    for (int idx = tid; idx < 64 * BANDW; idx += 256) {
        const int i = idx / BANDW;
        const int s = idx - i * BANDW;
        const int j = q0 + i + s - (APP - 1);
        float w = 0.f;
        if (j >= 0 && j < n) w = attb[(size_t)j * BANDP + (38 - s)];
        ws[i * 40 + s] = w;
    }

    for (int idx = tid; idx < 102 * 32; idx += 256) {
        const int row = idx >> 5;
        const int c4  = idx & 31;
        const int j = min(max(jbase + row, 0), n - 1);
        *reinterpret_cast<float4*>(&Vs[row * 128 + c4 * 4]) =
            *reinterpret_cast<const float4*>(V + (size_t)j * d + ch * 128 + c4 * 4);
    }
    __syncthreads();

    const int qg = tid >> 5;
    const int cg = tid & 31;

    float4 acc[8];
#pragma unroll
    for (int q = 0; q < 8; q++) acc[q] = make_float4(0.f, 0.f, 0.f, 0.f);

#pragma unroll
    for (int r = 0; r <= 45; r++) {
        const float4 v4 = *reinterpret_cast<const float4*>(&Vs[(qg * 8 + r) * 128 + cg * 4]);
#pragma unroll
        for (int q = 0; q < 8; q++) {
            const int s = r - q;
            if (s >= 0 && s < BANDW) {
                const float w = ws[(qg * 8 + q) * 40 + s];
                acc[q].x = fmaf(w, v4.x, acc[q].x);
                acc[q].y = fmaf(w, v4.y, acc[q].y);
                acc[q].z = fmaf(w, v4.z, acc[q].z);
                acc[q].w = fmaf(w, v4.w, acc[q].w);
            }
        }
    }
#pragma unroll
    for (int q = 0; q < 8; q++) {
        const int i = q0 + qg * 8 + q;
        *reinterpret_cast<float4*>(Y + (size_t)i * d + ch * 128 + cg * 4) = acc[q];
    }
}

// ---------------- residual + layernorm (merged branches) ---------------------
struct LN2 {
    const float* y[2]; const float* x[2];
    const float* g[2]; const float* b[2];
    float* dst[2]; int d[2]; int stride[2];
};

__global__ void ln_res2(LN2 pp)
{
    __shared__ float sh1[8], sh2[8];
    __shared__ float s_mu, s_rstd;
    const int br = blockIdx.y;
    const float* y = pp.y[br];
    const float* x = pp.x[br];
    const float* g = pp.g[br];
    const float* b = pp.b[br];
    float* dst = pp.dst[br];
    const int d = pp.d[br];
    const int dstride = pp.stride[br];

    const int i = blockIdx.x;
    const int lane = threadIdx.x & 31, wid = threadIdx.x >> 5;

    float sum = 0.f, sq = 0.f;
    for (int c = threadIdx.x; c < d; c += blockDim.x) {
        float v = y[(size_t)i * d + c] + x[(size_t)i * d + c];
        sum += v; sq = fmaf(v, v, sq);
    }
#pragma unroll
    for (int o = 16; o; o >>= 1) {
        sum += __shfl_down_sync(0xffffffffu, sum, o);
        sq  += __shfl_down_sync(0xffffffffu, sq,  o);
    }
    if (lane == 0) { sh1[wid] = sum; sh2[wid] = sq; }
    __syncthreads();
    if (wid == 0) {
        float s = (lane < 8) ? sh1[lane] : 0.f;
        float q = (lane < 8) ? sh2[lane] : 0.f;
#pragma unroll
        for (int o = 4; o; o >>= 1) {
            s += __shfl_down_sync(0xffffffffu, s, o);
            q += __shfl_down_sync(0xffffffffu, q, o);
        }
        if (lane == 0) {
            const float mu = s / d;
            float var = q / d - mu * mu;
            s_mu = mu;
            s_rstd = rsqrtf(var + 1e-6f);
        }
    }
    __syncthreads();
    const float mu = s_mu, rstd = s_rstd;
    for (int c = threadIdx.x; c < d; c += blockDim.x) {
        float v = y[(size_t)i * d + c] + x[(size_t)i * d + c];
        dst[(size_t)i * dstride + c] = (v - mu) * rstd * g[c] + b[c];
    }
}

// ---------------- fused LN(h) + sigmoid head ---------------------------------
__global__ void head_fused(const float* __restrict__ h, const float* __restrict__ g,
                           const float* __restrict__ b, const float* __restrict__ w,
                           const float* __restrict__ kd_b, float* __restrict__ out, int d)
{
    __shared__ float sh[8][5];
    const int i = blockIdx.x;
    const int lane = threadIdx.x & 31, wid = threadIdx.x >> 5;

    float sum = 0.f, sq = 0.f, hgw = 0.f, gw = 0.f, bw = 0.f;
    for (int c = threadIdx.x; c < d; c += blockDim.x) {
        const float hv = h[(size_t)i * d + c];
        const float gc = g[c], bc = b[c], wc = w[c];
        sum += hv; sq = fmaf(hv, hv, sq);
        const float gwc = gc * wc;
        hgw = fmaf(hv, gwc, hgw);
        gw += gwc;
        bw = fmaf(bc, wc, bw);
    }
#pragma unroll
    for (int o = 16; o; o >>= 1) {
        sum += __shfl_down_sync(0xffffffffu, sum, o);
        sq  += __shfl_down_sync(0xffffffffu, sq,  o);
        hgw += __shfl_down_sync(0xffffffffu, hgw, o);
        gw  += __shfl_down_sync(0xffffffffu, gw,  o);
        bw  += __shfl_down_sync(0xffffffffu, bw,  o);
    }
    if (lane == 0) {
        sh[wid][0] = sum; sh[wid][1] = sq; sh[wid][2] = hgw;
        sh[wid][3] = gw;  sh[wid][4] = bw;
    }
    __syncthreads();
    if (wid == 0 && lane == 0) {
        float s = 0.f, q = 0.f, hg = 0.f, gg = 0.f, bb = 0.f;
#pragma unroll
        for (int k = 0; k < 8; k++) {
            s += sh[k][0]; q += sh[k][1]; hg += sh[k][2];
            gg += sh[k][3]; bb += sh[k][4];
        }
        const float mu = s / d;
        const float var = q / d - mu * mu;
        const float rstd = rsqrtf(var + 1e-6f);
        const float sc = rstd * (hg - mu * gg) + bb + kd_b[0];
        out[i] = 1.f / (1.f + expf(-sc));
    }
}

// ---------------- scatter band attention into dense [N, 2N] output ----------
__global__ void scatter_att(const float* __restrict__ attv, const float* __restrict__ atta,
                            float* __restrict__ out, int n)
{
    const int i = blockIdx.x;
    const size_t base = (size_t)n + (size_t)i * 2u * (size_t)n;
    const int j0 = max(i - (APP - 1), 0);
    const int j1 = min(i + (APP - 1), n - 1);
    for (int k = threadIdx.x; k <= j1 - j0; k += blockDim.x) {
        const int j = j0 + k;
        const float av = attv[(size_t)i * BANDP + (j - i + (APP - 1))];
        const float aa = atta[(size_t)i * BANDP + (j - i + (APP - 1))];
        out[base + j]     = av;
        out[base + n + j] = aa;
    }
}

// ---------------- launch ------------------------------------------------------
extern "C" void kernel_launch(void* const* d_in, const int* in_sizes, int n_in,
                              void* d_out, int out_size)
{
    const float* x     = (const float*)d_in[0];
    const float* xa    = (const float*)d_in[1];
    const float* Wk_v  = (const float*)d_in[4];
    const float* Wq_v  = (const float*)d_in[5];
    const float* Wv_v  = (const float*)d_in[6];
    const float* Wo_v  = (const float*)d_in[7];
    const float* Wk_a  = (const float*)d_in[8];
    const float* Wq_a  = (const float*)d_in[9];
    const float* Wv_a  = (const float*)d_in[10];
    const float* Wo_a  = (const float*)d_in[11];
    const float* ka_w  = (const float*)d_in[12];
    const float* ka_b  = (const float*)d_in[13];
    const float* kd_w  = (const float*)d_in[14];
    const float* kd_b  = (const float*)d_in[15];
    const float* ln_y_g  = (const float*)d_in[16];
    const float* ln_y_b  = (const float*)d_in[17];
    const float* ln_ya_g = (const float*)d_in[18];
    const float* ln_ya_b = (const float*)d_in[19];
    const float* ln_ka_g = (const float*)d_in[20];
    const float* ln_ka_b = (const float*)d_in[21];

    const int n = in_sizes[0] / DV;   // 6144

    cudaFuncSetAttribute(tgemm, cudaFuncAttributeMaxDynamicSharedMemorySize, TG_SMEM);
    cudaFuncSetAttribute(band_att_mma, cudaFuncAttributeMaxDynamicSharedMemorySize, BA_SMEM);
    cudaFuncSetAttribute(band_apply_c, cudaFuncAttributeMaxDynamicSharedMemorySize, BP_SMEM);

    float *Kv, *Qv, *Vv, *Yv, *Yov, *Ka, *Qa, *Va, *Ya, *Yoa, *attv, *atta, *ycomb, *h;
    cudaGetSymbolAddress((void**)&Kv,  g_Kv);
    cudaGetSymbolAddress((void**)&Qv,  g_Qv);
    cudaGetSymbolAddress((void**)&Vv,  g_Vv);
    cudaGetSymbolAddress((void**)&Yv,  g_Yv);
    cudaGetSymbolAddress((void**)&Yov, g_Yov);
    cudaGetSymbolAddress((void**)&Ka,  g_Ka);
    cudaGetSymbolAddress((void**)&Qa,  g_Qa);
    cudaGetSymbolAddress((void**)&Va,  g_Va);
    cudaGetSymbolAddress((void**)&Ya,  g_Ya);
    cudaGetSymbolAddress((void**)&Yoa, g_Yoa);
    cudaGetSymbolAddress((void**)&attv, g_attv);
    cudaGetSymbolAddress((void**)&atta, g_atta);
    cudaGetSymbolAddress((void**)&ycomb, g_ycomb);
    cudaGetSymbolAddress((void**)&h,   g_h);

    float* WqT = Kv;                 // [1024,1024]
    float* WkT = Kv + 1024 * 1024;   // [1024,1024]
    float* Mt  = Kv + 2 * 1024 * 1024; // [1024,1024] = Wk^T @ Wq
    float* Pv  = Qv;                 // [N,1024] = 0.06 * x @ (Wq^T Wk)

    float* out = (float*)d_out;
    const size_t full_elems = (size_t)n + 2ull * (size_t)n * (size_t)n;
    const size_t clear = ((size_t)out_size >= full_elems) ? full_elems : (size_t)out_size;
    cudaMemsetAsync(out, 0, clear * sizeof(float), 0);

    const int nb = n / 64;   // 96 band blocks

    // --- transposes: WqT = Wq^T, WkT = Wk^T ---
    transpose2<<<dim3(32, 32, 2), dim3(32, 8)>>>(Wq_v, WqT, Wk_v, WkT, DV);

    // --- Mt = tgemm(WkT, WqT) = Wk^T @ Wq  (64 CTAs) ---
    {
        TG p; p.A0 = p.A1 = p.A2 = WkT;
        p.B0 = p.B1 = p.B2 = WqT;
        p.C0 = p.C1 = p.C2 = Mt;
        p.a0 = p.a1 = p.a2 = 1.f;
        p.bias = nullptr; p.relu = 0;
        p.K = DV; p.lda = DV; p.ldb = DV; p.ldc = DV;
        tgemm<<<dim3(DV / 128, DV / 128, 1), 256, TG_SMEM>>>(p);
    }

    // --- audio QKV (batched z, unchanged) ---
    {
        TG p; p.A0 = p.A1 = p.A2 = xa;
        p.B0 = Wk_a; p.B1 = Wq_a; p.B2 = Wv_a;
        p.C0 = Ka;   p.C1 = Qa;   p.C2 = Va;
        p.a0 = 1.f;  p.a1 = 0.06f; p.a2 = 1.f;
        p.bias = nullptr; p.relu = 0;
        p.K = DA; p.lda = DA; p.ldb = DA; p.ldc = DA;
        tgemm<<<dim3(DA / 128, n / 128, 3), 256, TG_SMEM>>>(p);
    }

    // --- video: V = x@Wv^T ;  P = 0.06 * x@Mt^T = 0.06 * x Wq^T Wk ---
    {
        TG p; p.A0 = p.A1 = p.A2 = x;
        p.B0 = Wv_v; p.B1 = Mt;  p.B2 = Mt;
        p.C0 = Vv;   p.C1 = Pv;  p.C2 = Pv;
        p.a0 = 1.f;  p.a1 = 0.06f; p.a2 = 0.06f;
        p.bias = nullptr; p.relu = 0;
        p.K = DV; p.lda = DV; p.ldb = DV; p.ldc = DV;
        tgemm<<<dim3(DV / 128, n / 128, 2), 256, TG_SMEM>>>(p);
    }

    // --- merged band attention: video logits = P @ x^T, audio = Qa @ Ka^T ---
    {
        BA2 p;
        p.Q[0] = Pv; p.Km[0] = x;  p.attb[0] = attv; p.d[0] = DV;
        p.Q[1] = Qa; p.Km[1] = Ka; p.attb[1] = atta; p.d[1] = DA;
        p.n = n;
        band_att_mma<<<dim3(nb, 2), 256, BA_SMEM>>>(p);
    }

    // --- chunk-parallel band apply ---
    band_apply_c<<<dim3(nb, DV / 128), 256, BP_SMEM>>>(attv, Vv, Yv, n, DV);
    band_apply_c<<<dim3(nb, DA / 128), 256, BP_SMEM>>>(atta, Va, Ya, n, DA);

    // --- video Wo ---
    {
        TG p; p.A0 = p.A1 = p.A2 = Yv;
        p.B0 = p.B1 = p.B2 = Wo_v;
        p.C0 = p.C1 = p.C2 = Yov;
        p.a0 = p.a1 = p.a2 = 1.f;
        p.bias = nullptr; p.relu = 0;
        p.K = DV; p.lda = DV; p.ldb = DV; p.ldc = DV;
        tgemm<<<dim3(DV / 128, n / 128, 1), 256, TG_SMEM>>>(p);
    }
    // --- audio Wo ---
    {
        TG p; p.A0 = p.A1 = p.A2 = Ya;
        p.B0 = p.B1 = p.B2 = Wo_a;
        p.C0 = p.C1 = p.C2 = Yoa;
        p.a0 = p.a1 = p.a2 = 1.f;
        p.bias = nullptr; p.relu = 0;
        p.K = DA; p.lda = DA; p.ldb = DA; p.ldc = DA;
        tgemm<<<dim3(DA / 128, n / 128, 1), 256, TG_SMEM>>>(p);
    }

    // --- merged residual LN (video + audio) -> ycomb ---
    {
        LN2 p;
        p.y[0] = Yov; p.x[0] = x;  p.g[0] = ln_y_g;  p.b[0] = ln_y_b;
        p.dst[0] = ycomb;      p.d[0] = DV; p.stride[0] = DC;
        p.y[1] = Yoa; p.x[1] = xa; p.g[1] = ln_ya_g; p.b[1] = ln_ya_b;
        p.dst[1] = ycomb + DV; p.d[1] = DA; p.stride[1] = DC;
        ln_res2<<<dim3(n, 2), 256>>>(p);
    }

    // --- MLP head GEMM ---
    {
        TG p; p.A0 = p.A1 = p.A2 = ycomb;
        p.B0 = p.B1 = p.B2 = ka_w;
        p.C0 = p.C1 = p.C2 = h;
        p.a0 = p.a1 = p.a2 = 1.f;
        p.bias = ka_b; p.relu = 1;
        p.K = DC; p.lda = DC; p.ldb = DC; p.ldc = DH;
        tgemm<<<dim3(DH / 128, n / 128, 1), 256, TG_SMEM>>>(p);
    }

    // --- fused LN + sigmoid head ---
    head_fused<<<n, 256>>>(h, ln_ka_g, ln_ka_b, kd_w, kd_b, out, DH);

    // --- dense attention output ---
    if ((size_t)out_size >= full_elems)
        scatter_att<<<n, 64>>>(attv, atta, out, n);
}